// round 10
// baseline (speedup 1.0000x reference)
#include <cuda_runtime.h>
#include <math.h>

#define BB 256
#define NN 4096
#define KK 64
#define CS_STRIDE 68   // 64 + 4 pad; 272 bytes, keeps 16B alignment
#define DP_STRIDE 34   // 32 + 2 pad; even => 8B-aligned LDS.64 rows
#define AS_STRIDE 65
#define NGPART 64      // Gram partial chunks (64 columns each)
#define NUPART 64      // U partial chunks (64 columns each)

// ---------------- packed f32x2 helpers (Blackwell full-rate fp32) ------------
__device__ __forceinline__ void fma2(unsigned long long& acc, unsigned long long a,
                                     unsigned long long b) {
    asm("fma.rn.f32x2 %0, %1, %2, %0;" : "+l"(acc) : "l"(a), "l"(b));
}
__device__ __forceinline__ unsigned long long pack2(float lo, float hi) {
    unsigned long long r;
    asm("mov.b64 %0, {%1, %2};" : "=l"(r) : "f"(lo), "f"(hi));
    return r;
}
__device__ __forceinline__ void unpack2(unsigned long long v, float& lo, float& hi) {
    asm("mov.b64 {%0, %1}, %2;" : "=f"(lo), "=f"(hi) : "l"(v));
}

// ---------------- scratch (static device globals; no allocation) -------------
// g_Ct has one extra ZERO row at n = NN (.bss zero-init) for branch-free
// padded gathers in k_main.
__device__ float g_Ct[(NN + 1) * KK];        // C'[n][k] = C[k][n] * rsqrt(psi[n])
__device__ float g_rpsi[NN];                 // rsqrt(psi)
__device__ float g_lpsi[NN];                 // log(psi)
__device__ float g_Gpart[NGPART * KK * KK];  // partial Gram matrices   (1 MB)
__device__ float g_G[KK * KK];               // I + C' C'^T
__device__ float g_dp[BB * NN];              // masked residual / sqrt(psi)
__device__ int   g_idx[BB * NN];             // compacted unmasked indices (padded)
__device__ int   g_cnt[BB];
__device__ float g_scal[BB * 8];             // per-row scalar reductions
__device__ float g_Upart[NUPART * BB * KK];  // partial u vectors        (4 MB)

// ---------------- kernel 1: FUSED scale+transpose+Gram-partial ---------------
// One CTA per 64-column chunk: computes rsqrt/log(psi) for its chunk, scales
// C into smem (and g_Ct for downstream kernels), then computes the Gram
// partial directly from smem. Replaces the old k_prep + k_gpart pair.
__global__ void k_gprep(const float* __restrict__ C, const float* __restrict__ psi) {
    __shared__ float Cs[64 * CS_STRIDE];
    __shared__ float rps[64];
    int tid = threadIdx.x;
    int n0 = blockIdx.x * 64;      // grid = 64

    if (tid < 64) {
        float ps = psi[n0 + tid];
        float rp = rsqrtf(ps);
        rps[tid] = rp;
        g_rpsi[n0 + tid] = rp;
        g_lpsi[n0 + tid] = logf(ps);
    }
    __syncthreads();

    // load + scale + transpose: thread owns C row k, 16 consecutive n
    int k = tid & 63, ng = tid >> 6;          // ng: 0..3
    float vals[16];
#pragma unroll
    for (int i = 0; i < 4; i++) {
        float4 c4 = *(const float4*)(C + k * NN + n0 + ng * 16 + i * 4);
        int nb = ng * 16 + i * 4;
        vals[i * 4 + 0] = c4.x * rps[nb + 0];
        vals[i * 4 + 1] = c4.y * rps[nb + 1];
        vals[i * 4 + 2] = c4.z * rps[nb + 2];
        vals[i * 4 + 3] = c4.w * rps[nb + 3];
    }
#pragma unroll
    for (int i = 0; i < 16; i++) {
        int n = ng * 16 + i;
        Cs[n * CS_STRIDE + k] = vals[i];           // conflict-free (k = lane)
        g_Ct[(n0 + n) * KK + k] = vals[i];         // coalesced 128B per warp
    }
    __syncthreads();

    // Gram partial from smem
    int ty = tid >> 4, tx = tid & 15;
    unsigned long long acc2[2][4];
#pragma unroll
    for (int ip = 0; ip < 2; ip++)
#pragma unroll
        for (int j = 0; j < 4; j++) acc2[ip][j] = 0ull;
#pragma unroll 16
    for (int s = 0; s < 64; s++) {
        const unsigned long long* ap =
            (const unsigned long long*)&Cs[s * CS_STRIDE + ty * 4];
        unsigned long long a01 = ap[0], a23 = ap[1];
        float4 b4 = *(const float4*)&Cs[s * CS_STRIDE + tx * 4];
        unsigned long long bd0 = pack2(b4.x, b4.x), bd1 = pack2(b4.y, b4.y);
        unsigned long long bd2 = pack2(b4.z, b4.z), bd3 = pack2(b4.w, b4.w);
        fma2(acc2[0][0], a01, bd0); fma2(acc2[0][1], a01, bd1);
        fma2(acc2[0][2], a01, bd2); fma2(acc2[0][3], a01, bd3);
        fma2(acc2[1][0], a23, bd0); fma2(acc2[1][1], a23, bd1);
        fma2(acc2[1][2], a23, bd2); fma2(acc2[1][3], a23, bd3);
    }
    float* out = g_Gpart + blockIdx.x * KK * KK;
#pragma unroll
    for (int ip = 0; ip < 2; ip++)
#pragma unroll
        for (int j = 0; j < 4; j++) {
            float lo, hi;
            unpack2(acc2[ip][j], lo, hi);
            out[(ty * 4 + 2 * ip + 0) * KK + tx * 4 + j] = lo;
            out[(ty * 4 + 2 * ip + 1) * KK + tx * 4 + j] = hi;
        }
}

// ---------------- kernel 2: elementwise + compaction (block = 512) -----------
__global__ void k_ew(const float* __restrict__ targets, const float* __restrict__ rho,
                     const float* __restrict__ qs, const float* __restrict__ means) {
    __shared__ unsigned warptot[16];
    __shared__ float wred[5 * 16];
    int b = blockIdx.x, tid = threadIdx.x;
    int lane = tid & 31, w = tid >> 5;
    float rho_s = rho[0];
    float logrho = logf(rho_s);
    const float* tg = targets + b * NN;
    const float* qp = qs + b * NN;
    const float* mp = means + b * NN;

    float uni = 0.f, extra = 0.f, wd2 = 0.f, slogpsi = 0.f, nb = 0.f;
    unsigned mask = 0;   // bit it set => UNMASKED at n = it*512 + tid

#pragma unroll
    for (int it = 0; it < 8; it++) {
        int n = it * 512 + tid;
        float t = tg[n], qv = qp[n], mu = mp[n];
        bool masked = (t >= rho_s);
        float dpv = 0.0f;
        if (masked) {
            float lt = logf(t);
            dpv = (lt - mu) * g_rpsi[n];
            wd2 += dpv * dpv;
            slogpsi += g_lpsi[n];
            nb += 1.0f;
            extra += logf(qv) - lt;
        } else {
            uni += log1pf(-qv) - logrho;
            mask |= (1u << it);
        }
        g_dp[b * NN + n] = dpv;
    }

    unsigned cnt = __popc(mask);
    unsigned x = cnt;
#pragma unroll
    for (int o = 1; o < 32; o <<= 1) {
        unsigned y = __shfl_up_sync(0xffffffffu, x, o);
        if (lane >= o) x += y;
    }
    unsigned excl = x - cnt;
    if (lane == 31) warptot[w] = x;

    float vals[5] = {uni, extra, wd2, slogpsi, nb};
#pragma unroll
    for (int q5 = 0; q5 < 5; q5++) {
        float v = vals[q5];
#pragma unroll
        for (int off2 = 16; off2 > 0; off2 >>= 1) v += __shfl_xor_sync(0xffffffffu, v, off2);
        if (lane == 0) wred[q5 * 16 + w] = v;
    }
    __syncthreads();

    unsigned off = excl;
    for (int ww = 0; ww < w; ww++) off += warptot[ww];
    unsigned tot = 0;
#pragma unroll
    for (int ww = 0; ww < 16; ww++) tot += warptot[ww];

    unsigned mm = mask;
    int* idxp = g_idx + b * NN;
    while (mm) {
        int it = __ffs(mm) - 1;
        mm &= mm - 1;
        idxp[off++] = it * 512 + tid;
    }
    unsigned pad = ((tot + 63u) & ~63u) - tot;
    if ((unsigned)tid < pad) idxp[tot + tid] = NN;

    if (tid == 0) {
        g_cnt[b] = (int)tot;
#pragma unroll
        for (int q5 = 0; q5 < 5; q5++) {
            float s = 0.f;
#pragma unroll
            for (int ww = 0; ww < 16; ww++) s += wred[q5 * 16 + ww];
            g_scal[b * 8 + q5] = s;
        }
    }

    // side job: blocks 0..15 reduce the Gram partials (256 elems each)
    if (b < 16 && tid < 256) {
        int gi = b * 256 + tid;
        float s = 0.f;
#pragma unroll
        for (int p = 0; p < NGPART; p++) s += g_Gpart[p * KK * KK + gi];
        if ((gi >> 6) == (gi & 63)) s += 1.0f;
        g_G[gi] = s;
    }
}

// ---------------- kernel 3: partial U = dp @ Ct, grid (8 btiles, 64 chunks) --
__global__ void k_upart() {
    __shared__ float DPt[64 * DP_STRIDE];   // [n][b] transposed dp tile (32 rows)
    __shared__ float Cts[64 * CS_STRIDE];   // [n][k]
    int tid = threadIdx.x;
    int btile = blockIdx.x * 32;   // gridDim.x = 8
    int nch = blockIdx.y;          // gridDim.y = 64
    int n0 = nch * 64;

    {
        int r2 = tid >> 2, q2 = tid & 3;
        const float4* cs = (const float4*)(g_Ct + (n0 + r2) * KK + q2 * 16);
#pragma unroll
        for (int i = 0; i < 4; i++)
            *(float4*)&Cts[r2 * CS_STRIDE + q2 * 16 + i * 4] = cs[i];
    }
    {
        int r = tid >> 3, q = tid & 7;
        const float4* ds = (const float4*)(g_dp + (btile + r) * NN + n0 + q * 8);
        float4 d0 = ds[0], d1 = ds[1];
        int nb0 = q * 8;
        DPt[(nb0 + 0) * DP_STRIDE + r] = d0.x;
        DPt[(nb0 + 1) * DP_STRIDE + r] = d0.y;
        DPt[(nb0 + 2) * DP_STRIDE + r] = d0.z;
        DPt[(nb0 + 3) * DP_STRIDE + r] = d0.w;
        DPt[(nb0 + 4) * DP_STRIDE + r] = d1.x;
        DPt[(nb0 + 5) * DP_STRIDE + r] = d1.y;
        DPt[(nb0 + 6) * DP_STRIDE + r] = d1.z;
        DPt[(nb0 + 7) * DP_STRIDE + r] = d1.w;
    }
    __syncthreads();

    int ty = tid >> 4, tx = tid & 15;
    unsigned long long acc2[4] = {0ull, 0ull, 0ull, 0ull};
#pragma unroll 16
    for (int s = 0; s < 64; s++) {
        unsigned long long a01 =
            *(const unsigned long long*)&DPt[s * DP_STRIDE + 2 * ty];
        float4 b4 = *(const float4*)&Cts[s * CS_STRIDE + tx * 4];
        fma2(acc2[0], a01, pack2(b4.x, b4.x));
        fma2(acc2[1], a01, pack2(b4.y, b4.y));
        fma2(acc2[2], a01, pack2(b4.z, b4.z));
        fma2(acc2[3], a01, pack2(b4.w, b4.w));
    }
    float* outp = g_Upart + nch * BB * KK;
#pragma unroll
    for (int j = 0; j < 4; j++) {
        float lo, hi;
        unpack2(acc2[j], lo, hi);
        outp[(btile + 2 * ty + 0) * KK + tx * 4 + j] = lo;
        outp[(btile + 2 * ty + 1) * KK + tx * 4 + j] = hi;
    }
}

// ---------------- kernel 4: per-b correction SYRK + Cholesky + solve ---------
// 512 threads: halves the per-thread SYRK chain vs 256; Cholesky update gets
// 8-way row parallelism. Smem ~36.5KB (static limit respected).
__global__ void __launch_bounds__(512, 2) k_main(float* __restrict__ out) {
    __shared__ float Cs[64 * CS_STRIDE];
    __shared__ float As[64 * AS_STRIDE];
    __shared__ float ured[8][64];
    __shared__ float u_s[64], col_s[64], diag_s[64], z_s[64], lred[2];
    int b = blockIdx.x, tid = threadIdx.x;
    int ty = tid >> 4, tx = tid & 15;        // SYRK: rows (2ty,2ty+1), cols 4tx..
    int r = tid >> 3, q2 = tid & 7;          // staging: row r, 8-float group q2

    // parallel u-reduce: 64 partials split 8 ways across 512 threads
    {
        int kk = tid & 63, gg = tid >> 6;
        float s = 0.f;
#pragma unroll
        for (int p = 0; p < 8; p++)
            s += g_Upart[(gg * 8 + p) * BB * KK + b * KK + kk];
        ured[gg][kk] = s;
    }

    unsigned long long acc2[4] = {0ull, 0ull, 0ull, 0ull};

    int cnt = g_cnt[b];
    int tiles = (cnt + 63) >> 6;
    const int* idxp = g_idx + b * NN;

    float4 pre[2];
    if (tiles > 0) {
        int n = idxp[r];
        const float4* src = (const float4*)(g_Ct + n * KK + q2 * 8);
        pre[0] = src[0];
        pre[1] = src[1];
    }
    __syncthreads();                          // ured visible
    if (tid < 64) {
        float s = 0.f;
#pragma unroll
        for (int gg = 0; gg < 8; gg++) s += ured[gg][tid];
        u_s[tid] = s;
    }

    for (int t = 0; t < tiles; t++) {
        *(float4*)&Cs[r * CS_STRIDE + q2 * 8 + 0] = pre[0];
        *(float4*)&Cs[r * CS_STRIDE + q2 * 8 + 4] = pre[1];
        __syncthreads();
        if (t + 1 < tiles) {                  // register prefetch of next tile
            int n = idxp[(t + 1) * 64 + r];
            const float4* src = (const float4*)(g_Ct + n * KK + q2 * 8);
            pre[0] = src[0];
            pre[1] = src[1];
        }
#pragma unroll 16
        for (int s = 0; s < 64; s++) {
            unsigned long long a01 =
                *(const unsigned long long*)&Cs[s * CS_STRIDE + 2 * ty];
            float4 b4 = *(const float4*)&Cs[s * CS_STRIDE + tx * 4];
            fma2(acc2[0], a01, pack2(b4.x, b4.x));
            fma2(acc2[1], a01, pack2(b4.y, b4.y));
            fma2(acc2[2], a01, pack2(b4.z, b4.z));
            fma2(acc2[3], a01, pack2(b4.w, b4.w));
        }
        __syncthreads();
    }

    // As = G - S
#pragma unroll
    for (int j = 0; j < 4; j++) {
        float lo, hi;
        unpack2(acc2[j], lo, hi);
        int c0 = tx * 4 + j;
        As[(2 * ty + 0) * AS_STRIDE + c0] = g_G[(2 * ty + 0) * KK + c0] - lo;
        As[(2 * ty + 1) * AS_STRIDE + c0] = g_G[(2 * ty + 1) * KK + c0] - hi;
    }
    __syncthreads();

    // ---- Cholesky (lower), block-parallel, div-free update ----
    int urow = tid >> 6;       // 0..7
    int ucol = tid & 63;
    for (int j = 0; j < 64; j++) {
        float d = sqrtf(As[j * AS_STRIDE + j]);
        float inv = 1.0f / d;
        if (tid == 0) diag_s[j] = d;
        int i2 = j + 1 + tid;
        if (i2 < 64) {
            float v = As[i2 * AS_STRIDE + j] * inv;
            As[i2 * AS_STRIDE + j] = v;
            col_s[i2] = v;
        }
        __syncthreads();
        int cc = j + 1 + ucol;
        if (cc < 64) {
            float cv = col_s[cc];
            for (int rr = j + 1 + urow; rr < 64; rr += 8)
                As[rr * AS_STRIDE + cc] -= col_s[rr] * cv;
        }
        __syncthreads();
    }

    // ---- forward solve L z = u;  u^T A^-1 u = ||z||^2 ----
    if (tid < 64) z_s[tid] = u_s[tid];
    __syncthreads();
    float zz = 0.f;
    for (int j = 0; j < 64; j++) {
        float zj = z_s[j] / diag_s[j];
        zz += zj * zj;
        int rr = j + 1 + tid;
        if (rr < 64) z_s[rr] -= As[rr * AS_STRIDE + j] * zj;
        __syncthreads();
    }

    // ---- parallel logdet from diag ----
    if (tid < 64) {
        float lg = logf(diag_s[tid]);
#pragma unroll
        for (int o = 16; o > 0; o >>= 1) lg += __shfl_xor_sync(0xffffffffu, lg, o);
        if ((tid & 31) == 0) lred[tid >> 5] = lg;
    }
    __syncthreads();

    if (tid == 0) {
        float uni   = g_scal[b * 8 + 0];
        float extra = g_scal[b * 8 + 1];
        float wd2   = g_scal[b * 8 + 2];
        float slp   = g_scal[b * 8 + 3];
        float nb    = g_scal[b * 8 + 4];
        float logdetA = 2.0f * (lred[0] + lred[1]);
        const float LOG2PI = 1.8378770664093453f;
        float gauss = -0.5f * (nb * LOG2PI + (slp + logdetA) + (wd2 - zz));
        out[b] = uni + gauss + extra;
    }
}

// ---------------- launch ------------------------------------------------------
extern "C" void kernel_launch(void* const* d_in, const int* in_sizes, int n_in,
                              void* d_out, int out_size) {
    const float* targets = (const float*)d_in[0];
    const float* rho     = (const float*)d_in[1];
    const float* qs      = (const float*)d_in[2];
    const float* means   = (const float*)d_in[3];
    const float* C       = (const float*)d_in[4];
    const float* psi     = (const float*)d_in[5];
    float* out = (float*)d_out;

    k_gprep<<<NGPART, 256>>>(C, psi);
    k_ew<<<BB, 512>>>(targets, rho, qs, means);
    k_upart<<<dim3(8, NUPART), 256>>>();
    k_main<<<BB, 512>>>(out);
}

// round 11
// speedup vs baseline: 1.3151x; 1.3151x over previous
#include <cuda_runtime.h>
#include <math.h>

#define BB 256
#define NN 4096
#define KK 64
#define CS_STRIDE 68   // 64 + 4 pad; 272 bytes, keeps 16B alignment
#define DP_STRIDE 34   // 32 + 2 pad; even => 8B-aligned LDS.64 rows
#define AS_STRIDE 65
#define NGPART 64      // Gram partial chunks (64 columns each)
#define NUPART 64      // U partial chunks (64 columns each)

// ---------------- packed f32x2 helpers (Blackwell full-rate fp32) ------------
__device__ __forceinline__ void fma2(unsigned long long& acc, unsigned long long a,
                                     unsigned long long b) {
    asm("fma.rn.f32x2 %0, %1, %2, %0;" : "+l"(acc) : "l"(a), "l"(b));
}
__device__ __forceinline__ unsigned long long pack2(float lo, float hi) {
    unsigned long long r;
    asm("mov.b64 %0, {%1, %2};" : "=l"(r) : "f"(lo), "f"(hi));
    return r;
}
__device__ __forceinline__ void unpack2(unsigned long long v, float& lo, float& hi) {
    asm("mov.b64 {%0, %1}, %2;" : "=f"(lo), "=f"(hi) : "l"(v));
}

// ---------------- scratch (static device globals; no allocation) -------------
__device__ float g_Ct[(NN + 1) * KK];        // C'[n][k]; extra zero row at n=NN
__device__ float g_rpsi[NN];                 // rsqrt(psi)
__device__ float g_lpsi[NN];                 // log(psi)
__device__ float g_Gpart[NGPART * KK * KK];  // partial Gram matrices
__device__ float g_G[KK * KK];               // I + C' C'^T
__device__ float g_dp[BB * NN];              // masked residual / sqrt(psi)
__device__ int   g_idx[BB * NN];             // compacted unmasked indices (padded)
__device__ int   g_cnt[BB];
__device__ float g_scal[BB * 8];             // per-row scalar reductions
__device__ float g_Upart[NUPART * BB * KK];  // partial u vectors

// ---------------- kernel 1: FUSED scale+transpose+Gram-partial ---------------
__global__ void k_gprep(const float* __restrict__ C, const float* __restrict__ psi) {
    __shared__ float Cs[64 * CS_STRIDE];
    __shared__ float rps[64];
    int tid = threadIdx.x;
    int n0 = blockIdx.x * 64;      // grid = 64

    if (tid < 64) {
        float ps = psi[n0 + tid];
        float rp = rsqrtf(ps);
        rps[tid] = rp;
        g_rpsi[n0 + tid] = rp;
        g_lpsi[n0 + tid] = logf(ps);
    }
    __syncthreads();

    int k = tid & 63, ng = tid >> 6;
    float vals[16];
#pragma unroll
    for (int i = 0; i < 4; i++) {
        float4 c4 = *(const float4*)(C + k * NN + n0 + ng * 16 + i * 4);
        int nb = ng * 16 + i * 4;
        vals[i * 4 + 0] = c4.x * rps[nb + 0];
        vals[i * 4 + 1] = c4.y * rps[nb + 1];
        vals[i * 4 + 2] = c4.z * rps[nb + 2];
        vals[i * 4 + 3] = c4.w * rps[nb + 3];
    }
#pragma unroll
    for (int i = 0; i < 16; i++) {
        int n = ng * 16 + i;
        Cs[n * CS_STRIDE + k] = vals[i];
        g_Ct[(n0 + n) * KK + k] = vals[i];
    }
    __syncthreads();

    int ty = tid >> 4, tx = tid & 15;
    unsigned long long acc2[2][4];
#pragma unroll
    for (int ip = 0; ip < 2; ip++)
#pragma unroll
        for (int j = 0; j < 4; j++) acc2[ip][j] = 0ull;
#pragma unroll 16
    for (int s = 0; s < 64; s++) {
        const unsigned long long* ap =
            (const unsigned long long*)&Cs[s * CS_STRIDE + ty * 4];
        unsigned long long a01 = ap[0], a23 = ap[1];
        float4 b4 = *(const float4*)&Cs[s * CS_STRIDE + tx * 4];
        unsigned long long bd0 = pack2(b4.x, b4.x), bd1 = pack2(b4.y, b4.y);
        unsigned long long bd2 = pack2(b4.z, b4.z), bd3 = pack2(b4.w, b4.w);
        fma2(acc2[0][0], a01, bd0); fma2(acc2[0][1], a01, bd1);
        fma2(acc2[0][2], a01, bd2); fma2(acc2[0][3], a01, bd3);
        fma2(acc2[1][0], a23, bd0); fma2(acc2[1][1], a23, bd1);
        fma2(acc2[1][2], a23, bd2); fma2(acc2[1][3], a23, bd3);
    }
    float* out = g_Gpart + blockIdx.x * KK * KK;
#pragma unroll
    for (int ip = 0; ip < 2; ip++)
#pragma unroll
        for (int j = 0; j < 4; j++) {
            float lo, hi;
            unpack2(acc2[ip][j], lo, hi);
            out[(ty * 4 + 2 * ip + 0) * KK + tx * 4 + j] = lo;
            out[(ty * 4 + 2 * ip + 1) * KK + tx * 4 + j] = hi;
        }
}

// ---------------- kernel 2: elementwise + compaction (block = 512) -----------
__global__ void k_ew(const float* __restrict__ targets, const float* __restrict__ rho,
                     const float* __restrict__ qs, const float* __restrict__ means) {
    __shared__ unsigned warptot[16];
    __shared__ float wred[5 * 16];
    int b = blockIdx.x, tid = threadIdx.x;
    int lane = tid & 31, w = tid >> 5;
    float rho_s = rho[0];
    float logrho = logf(rho_s);
    const float* tg = targets + b * NN;
    const float* qp = qs + b * NN;
    const float* mp = means + b * NN;

    float uni = 0.f, extra = 0.f, wd2 = 0.f, slogpsi = 0.f, nb = 0.f;
    unsigned mask = 0;

#pragma unroll
    for (int it = 0; it < 8; it++) {
        int n = it * 512 + tid;
        float t = tg[n], qv = qp[n], mu = mp[n];
        bool masked = (t >= rho_s);
        float dpv = 0.0f;
        if (masked) {
            float lt = logf(t);
            dpv = (lt - mu) * g_rpsi[n];
            wd2 += dpv * dpv;
            slogpsi += g_lpsi[n];
            nb += 1.0f;
            extra += logf(qv) - lt;
        } else {
            uni += log1pf(-qv) - logrho;
            mask |= (1u << it);
        }
        g_dp[b * NN + n] = dpv;
    }

    unsigned cnt = __popc(mask);
    unsigned x = cnt;
#pragma unroll
    for (int o = 1; o < 32; o <<= 1) {
        unsigned y = __shfl_up_sync(0xffffffffu, x, o);
        if (lane >= o) x += y;
    }
    unsigned excl = x - cnt;
    if (lane == 31) warptot[w] = x;

    float vals[5] = {uni, extra, wd2, slogpsi, nb};
#pragma unroll
    for (int q5 = 0; q5 < 5; q5++) {
        float v = vals[q5];
#pragma unroll
        for (int off2 = 16; off2 > 0; off2 >>= 1) v += __shfl_xor_sync(0xffffffffu, v, off2);
        if (lane == 0) wred[q5 * 16 + w] = v;
    }
    __syncthreads();

    unsigned off = excl;
    for (int ww = 0; ww < w; ww++) off += warptot[ww];
    unsigned tot = 0;
#pragma unroll
    for (int ww = 0; ww < 16; ww++) tot += warptot[ww];

    unsigned mm = mask;
    int* idxp = g_idx + b * NN;
    while (mm) {
        int it = __ffs(mm) - 1;
        mm &= mm - 1;
        idxp[off++] = it * 512 + tid;
    }
    unsigned pad = ((tot + 63u) & ~63u) - tot;
    if ((unsigned)tid < pad) idxp[tot + tid] = NN;

    if (tid == 0) {
        g_cnt[b] = (int)tot;
#pragma unroll
        for (int q5 = 0; q5 < 5; q5++) {
            float s = 0.f;
#pragma unroll
            for (int ww = 0; ww < 16; ww++) s += wred[q5 * 16 + ww];
            g_scal[b * 8 + q5] = s;
        }
    }

    if (b < 16 && tid < 256) {
        int gi = b * 256 + tid;
        float s = 0.f;
#pragma unroll
        for (int p = 0; p < NGPART; p++) s += g_Gpart[p * KK * KK + gi];
        if ((gi >> 6) == (gi & 63)) s += 1.0f;
        g_G[gi] = s;
    }
}

// ---------------- kernel 3: partial U = dp @ Ct, grid (8 btiles, 64 chunks) --
__global__ void k_upart() {
    __shared__ float DPt[64 * DP_STRIDE];
    __shared__ float Cts[64 * CS_STRIDE];
    int tid = threadIdx.x;
    int btile = blockIdx.x * 32;   // gridDim.x = 8
    int nch = blockIdx.y;          // gridDim.y = 64
    int n0 = nch * 64;

    {
        int r2 = tid >> 2, q2 = tid & 3;
        const float4* cs = (const float4*)(g_Ct + (n0 + r2) * KK + q2 * 16);
#pragma unroll
        for (int i = 0; i < 4; i++)
            *(float4*)&Cts[r2 * CS_STRIDE + q2 * 16 + i * 4] = cs[i];
    }
    {
        int r = tid >> 3, q = tid & 7;
        const float4* ds = (const float4*)(g_dp + (btile + r) * NN + n0 + q * 8);
        float4 d0 = ds[0], d1 = ds[1];
        int nb0 = q * 8;
        DPt[(nb0 + 0) * DP_STRIDE + r] = d0.x;
        DPt[(nb0 + 1) * DP_STRIDE + r] = d0.y;
        DPt[(nb0 + 2) * DP_STRIDE + r] = d0.z;
        DPt[(nb0 + 3) * DP_STRIDE + r] = d0.w;
        DPt[(nb0 + 4) * DP_STRIDE + r] = d1.x;
        DPt[(nb0 + 5) * DP_STRIDE + r] = d1.y;
        DPt[(nb0 + 6) * DP_STRIDE + r] = d1.z;
        DPt[(nb0 + 7) * DP_STRIDE + r] = d1.w;
    }
    __syncthreads();

    int ty = tid >> 4, tx = tid & 15;
    unsigned long long acc2[4] = {0ull, 0ull, 0ull, 0ull};
#pragma unroll 16
    for (int s = 0; s < 64; s++) {
        unsigned long long a01 =
            *(const unsigned long long*)&DPt[s * DP_STRIDE + 2 * ty];
        float4 b4 = *(const float4*)&Cts[s * CS_STRIDE + tx * 4];
        fma2(acc2[0], a01, pack2(b4.x, b4.x));
        fma2(acc2[1], a01, pack2(b4.y, b4.y));
        fma2(acc2[2], a01, pack2(b4.z, b4.z));
        fma2(acc2[3], a01, pack2(b4.w, b4.w));
    }
    float* outp = g_Upart + nch * BB * KK;
#pragma unroll
    for (int j = 0; j < 4; j++) {
        float lo, hi;
        unpack2(acc2[j], lo, hi);
        outp[(btile + 2 * ty + 0) * KK + tx * 4 + j] = lo;
        outp[(btile + 2 * ty + 1) * KK + tx * 4 + j] = hi;
    }
}

// ---------------- kernel 4: per-b correction SYRK + LDL^T + solve ------------
// 256 threads (proven R9 SYRK operating point). LDL^T outer-product form:
// ONE barrier per column (updates write only cols > j, read only col j).
// Diagonal p_j is never overwritten -> logdet = sum log p_j at the end.
// Forward solve runs on warp 0 with shuffles (no block barriers).
__global__ void __launch_bounds__(256, 2) k_main(float* __restrict__ out) {
    __shared__ float Cs[64 * CS_STRIDE];
    __shared__ float As[64 * AS_STRIDE];
    __shared__ float ured[4][64];
    __shared__ float u_s[64], rinv_s[64], lred[2];
    __shared__ float zz_s;
    int b = blockIdx.x, tid = threadIdx.x;
    int ty = tid >> 4, tx = tid & 15;
    int r = tid >> 2, q = tid & 3;

    // parallel u-reduce: 64 partials split 4 ways across 256 threads
    {
        int kk = tid & 63, gg = tid >> 6;
        float s = 0.f;
#pragma unroll
        for (int p = 0; p < 16; p++)
            s += g_Upart[(gg * 16 + p) * BB * KK + b * KK + kk];
        ured[gg][kk] = s;
    }

    unsigned long long acc2[2][4];
#pragma unroll
    for (int ip = 0; ip < 2; ip++)
#pragma unroll
        for (int j = 0; j < 4; j++) acc2[ip][j] = 0ull;

    int cnt = g_cnt[b];
    int tiles = (cnt + 63) >> 6;
    const int* idxp = g_idx + b * NN;

    float4 pre[4];
    if (tiles > 0) {
        int n = idxp[r];
        const float4* src = (const float4*)(g_Ct + n * KK + q * 16);
#pragma unroll
        for (int i = 0; i < 4; i++) pre[i] = src[i];
    }
    __syncthreads();
    if (tid < 64)
        u_s[tid] = ured[0][tid] + ured[1][tid] + ured[2][tid] + ured[3][tid];

    for (int t = 0; t < tiles; t++) {
#pragma unroll
        for (int i = 0; i < 4; i++)
            *(float4*)&Cs[r * CS_STRIDE + q * 16 + i * 4] = pre[i];
        __syncthreads();
        if (t + 1 < tiles) {
            int n = idxp[(t + 1) * 64 + r];
            const float4* src = (const float4*)(g_Ct + n * KK + q * 16);
#pragma unroll
            for (int i = 0; i < 4; i++) pre[i] = src[i];
        }
#pragma unroll 16
        for (int s = 0; s < 64; s++) {
            const unsigned long long* ap =
                (const unsigned long long*)&Cs[s * CS_STRIDE + ty * 4];
            unsigned long long a01 = ap[0], a23 = ap[1];
            float4 b4 = *(const float4*)&Cs[s * CS_STRIDE + tx * 4];
            unsigned long long bd0 = pack2(b4.x, b4.x), bd1 = pack2(b4.y, b4.y);
            unsigned long long bd2 = pack2(b4.z, b4.z), bd3 = pack2(b4.w, b4.w);
            fma2(acc2[0][0], a01, bd0); fma2(acc2[0][1], a01, bd1);
            fma2(acc2[0][2], a01, bd2); fma2(acc2[0][3], a01, bd3);
            fma2(acc2[1][0], a23, bd0); fma2(acc2[1][1], a23, bd1);
            fma2(acc2[1][2], a23, bd2); fma2(acc2[1][3], a23, bd3);
        }
        __syncthreads();
    }

    // As = G - S
#pragma unroll
    for (int ip = 0; ip < 2; ip++)
#pragma unroll
        for (int j = 0; j < 4; j++) {
            float lo, hi;
            unpack2(acc2[ip][j], lo, hi);
            int r0 = ty * 4 + 2 * ip, c0 = tx * 4 + j;
            As[(r0 + 0) * AS_STRIDE + c0] = g_G[(r0 + 0) * KK + c0] - lo;
            As[(r0 + 1) * AS_STRIDE + c0] = g_G[(r0 + 1) * KK + c0] - hi;
        }
    __syncthreads();

    // ---- LDL^T factorization: one barrier per column ----
    int urow = tid >> 6;       // 0..3
    int ucol = tid & 63;       // 0..63
    for (int j = 0; j < 64; j++) {
        float rinv = 1.0f / As[j * AS_STRIDE + j];   // p_j stays at the diagonal
        if (tid == 0) rinv_s[j] = rinv;
        int cc = j + 1 + ucol;
        if (cc < 64) {
            float f = As[cc * AS_STRIDE + j] * rinv;
            for (int rr = j + 1 + urow; rr < 64; rr += 4)
                As[rr * AS_STRIDE + cc] -= As[rr * AS_STRIDE + j] * f;
        }
        __syncthreads();
    }

    // ---- forward solve on warp 0 (no block barriers): y = L^{-1} u,
    //      quad = sum y_j^2 / p_j ----
    if (tid < 32) {
        float y0 = u_s[tid], y1 = u_s[tid + 32];
        float zz = 0.f;
        for (int j = 0; j < 64; j++) {
            float yj;
            if (j < 32) yj = __shfl_sync(0xffffffffu, y0, j);
            else        yj = __shfl_sync(0xffffffffu, y1, j - 32);
            float wv = yj * rinv_s[j];
            zz += yj * wv;
            if (tid > j)      y0 -= As[tid * AS_STRIDE + j] * wv;
            if (tid + 32 > j) y1 -= As[(tid + 32) * AS_STRIDE + j] * wv;
        }
        if (tid == 0) zz_s = zz;
    }

    // ---- parallel logdet from untouched diagonal p_j ----
    if (tid >= 64 && tid < 128) {
        int j = tid - 64;
        float lg = logf(As[j * AS_STRIDE + j]);
#pragma unroll
        for (int o = 16; o > 0; o >>= 1) lg += __shfl_xor_sync(0xffffffffu, lg, o);
        if ((j & 31) == 0) lred[j >> 5] = lg;
    }
    __syncthreads();

    if (tid == 0) {
        float uni   = g_scal[b * 8 + 0];
        float extra = g_scal[b * 8 + 1];
        float wd2   = g_scal[b * 8 + 2];
        float slp   = g_scal[b * 8 + 3];
        float nb    = g_scal[b * 8 + 4];
        float logdetA = lred[0] + lred[1];
        const float LOG2PI = 1.8378770664093453f;
        float gauss = -0.5f * (nb * LOG2PI + (slp + logdetA) + (wd2 - zz_s));
        out[b] = uni + gauss + extra;
    }
}

// ---------------- launch ------------------------------------------------------
extern "C" void kernel_launch(void* const* d_in, const int* in_sizes, int n_in,
                              void* d_out, int out_size) {
    const float* targets = (const float*)d_in[0];
    const float* rho     = (const float*)d_in[1];
    const float* qs      = (const float*)d_in[2];
    const float* means   = (const float*)d_in[3];
    const float* C       = (const float*)d_in[4];
    const float* psi     = (const float*)d_in[5];
    float* out = (float*)d_out;

    k_gprep<<<NGPART, 256>>>(C, psi);
    k_ew<<<BB, 512>>>(targets, rho, qs, means);
    k_upart<<<dim3(8, NUPART), 256>>>();
    k_main<<<BB, 256>>>(out);
}

// round 12
// speedup vs baseline: 1.3268x; 1.0089x over previous
#include <cuda_runtime.h>
#include <math.h>

#define BB 256
#define NN 4096
#define KK 64
#define CS_STRIDE 68   // 64 + 4 pad; 272 bytes, keeps 16B alignment
#define DP_STRIDE 34   // 32 + 2 pad; even => 8B-aligned LDS.64 rows
#define AS_STRIDE 65
#define NGPART 64      // Gram partial chunks (64 columns each)
#define NUPART 64      // U partial chunks (64 columns each)
#define NSPLIT 2       // SYRK partial split per batch row

// ---------------- packed f32x2 helpers (Blackwell full-rate fp32) ------------
__device__ __forceinline__ void fma2(unsigned long long& acc, unsigned long long a,
                                     unsigned long long b) {
    asm("fma.rn.f32x2 %0, %1, %2, %0;" : "+l"(acc) : "l"(a), "l"(b));
}
__device__ __forceinline__ unsigned long long pack2(float lo, float hi) {
    unsigned long long r;
    asm("mov.b64 %0, {%1, %2};" : "=l"(r) : "f"(lo), "f"(hi));
    return r;
}
__device__ __forceinline__ void unpack2(unsigned long long v, float& lo, float& hi) {
    asm("mov.b64 {%0, %1}, %2;" : "=f"(lo), "=f"(hi) : "l"(v));
}

// ---------------- scratch (static device globals; no allocation) -------------
__device__ float g_Ct[(NN + 1) * KK];        // C'[n][k]; extra zero row at n=NN
__device__ float g_rpsi[NN];                 // rsqrt(psi)
__device__ float g_lpsi[NN];                 // log(psi)
__device__ float g_Gpart[NGPART * KK * KK];  // partial Gram matrices
__device__ float g_G[KK * KK];               // I + C' C'^T
__device__ float g_dp[BB * NN];              // masked residual / sqrt(psi)
__device__ int   g_idx[BB * NN];             // compacted unmasked indices (padded)
__device__ int   g_cnt[BB];
__device__ float g_scal[BB * 8];             // per-row scalar reductions
__device__ float g_Upart[NUPART * BB * KK];  // partial u vectors
__device__ float g_Spart[NSPLIT * BB * KK * KK]; // partial correction SYRKs (8 MB)

// ---------------- kernel 1: FUSED scale+transpose+Gram-partial ---------------
__global__ void k_gprep(const float* __restrict__ C, const float* __restrict__ psi) {
    __shared__ float Cs[64 * CS_STRIDE];
    __shared__ float rps[64];
    int tid = threadIdx.x;
    int n0 = blockIdx.x * 64;      // grid = 64

    if (tid < 64) {
        float ps = psi[n0 + tid];
        float rp = rsqrtf(ps);
        rps[tid] = rp;
        g_rpsi[n0 + tid] = rp;
        g_lpsi[n0 + tid] = logf(ps);
    }
    __syncthreads();

    int k = tid & 63, ng = tid >> 6;
    float vals[16];
#pragma unroll
    for (int i = 0; i < 4; i++) {
        float4 c4 = *(const float4*)(C + k * NN + n0 + ng * 16 + i * 4);
        int nb = ng * 16 + i * 4;
        vals[i * 4 + 0] = c4.x * rps[nb + 0];
        vals[i * 4 + 1] = c4.y * rps[nb + 1];
        vals[i * 4 + 2] = c4.z * rps[nb + 2];
        vals[i * 4 + 3] = c4.w * rps[nb + 3];
    }
#pragma unroll
    for (int i = 0; i < 16; i++) {
        int n = ng * 16 + i;
        Cs[n * CS_STRIDE + k] = vals[i];
        g_Ct[(n0 + n) * KK + k] = vals[i];
    }
    __syncthreads();

    int ty = tid >> 4, tx = tid & 15;
    unsigned long long acc2[2][4];
#pragma unroll
    for (int ip = 0; ip < 2; ip++)
#pragma unroll
        for (int j = 0; j < 4; j++) acc2[ip][j] = 0ull;
#pragma unroll 16
    for (int s = 0; s < 64; s++) {
        ulonglong2 aa = *(const ulonglong2*)&Cs[s * CS_STRIDE + ty * 4];
        unsigned long long a01 = aa.x, a23 = aa.y;
        float4 b4 = *(const float4*)&Cs[s * CS_STRIDE + tx * 4];
        unsigned long long bd0 = pack2(b4.x, b4.x), bd1 = pack2(b4.y, b4.y);
        unsigned long long bd2 = pack2(b4.z, b4.z), bd3 = pack2(b4.w, b4.w);
        fma2(acc2[0][0], a01, bd0); fma2(acc2[0][1], a01, bd1);
        fma2(acc2[0][2], a01, bd2); fma2(acc2[0][3], a01, bd3);
        fma2(acc2[1][0], a23, bd0); fma2(acc2[1][1], a23, bd1);
        fma2(acc2[1][2], a23, bd2); fma2(acc2[1][3], a23, bd3);
    }
    float* out = g_Gpart + blockIdx.x * KK * KK;
#pragma unroll
    for (int ip = 0; ip < 2; ip++)
#pragma unroll
        for (int j = 0; j < 4; j++) {
            float lo, hi;
            unpack2(acc2[ip][j], lo, hi);
            out[(ty * 4 + 2 * ip + 0) * KK + tx * 4 + j] = lo;
            out[(ty * 4 + 2 * ip + 1) * KK + tx * 4 + j] = hi;
        }
}

// ---------------- kernel 2: elementwise + compaction (block = 512) -----------
__global__ void k_ew(const float* __restrict__ targets, const float* __restrict__ rho,
                     const float* __restrict__ qs, const float* __restrict__ means) {
    __shared__ unsigned warptot[16];
    __shared__ float wred[5 * 16];
    int b = blockIdx.x, tid = threadIdx.x;
    int lane = tid & 31, w = tid >> 5;
    float rho_s = rho[0];
    float logrho = logf(rho_s);
    const float* tg = targets + b * NN;
    const float* qp = qs + b * NN;
    const float* mp = means + b * NN;

    float uni = 0.f, extra = 0.f, wd2 = 0.f, slogpsi = 0.f, nb = 0.f;
    unsigned mask = 0;

#pragma unroll
    for (int it = 0; it < 8; it++) {
        int n = it * 512 + tid;
        float t = tg[n], qv = qp[n], mu = mp[n];
        bool masked = (t >= rho_s);
        float dpv = 0.0f;
        if (masked) {
            float lt = logf(t);
            dpv = (lt - mu) * g_rpsi[n];
            wd2 += dpv * dpv;
            slogpsi += g_lpsi[n];
            nb += 1.0f;
            extra += logf(qv) - lt;
        } else {
            uni += log1pf(-qv) - logrho;
            mask |= (1u << it);
        }
        g_dp[b * NN + n] = dpv;
    }

    unsigned cnt = __popc(mask);
    unsigned x = cnt;
#pragma unroll
    for (int o = 1; o < 32; o <<= 1) {
        unsigned y = __shfl_up_sync(0xffffffffu, x, o);
        if (lane >= o) x += y;
    }
    unsigned excl = x - cnt;
    if (lane == 31) warptot[w] = x;

    float vals[5] = {uni, extra, wd2, slogpsi, nb};
#pragma unroll
    for (int q5 = 0; q5 < 5; q5++) {
        float v = vals[q5];
#pragma unroll
        for (int off2 = 16; off2 > 0; off2 >>= 1) v += __shfl_xor_sync(0xffffffffu, v, off2);
        if (lane == 0) wred[q5 * 16 + w] = v;
    }
    __syncthreads();

    unsigned off = excl;
    for (int ww = 0; ww < w; ww++) off += warptot[ww];
    unsigned tot = 0;
#pragma unroll
    for (int ww = 0; ww < 16; ww++) tot += warptot[ww];

    unsigned mm = mask;
    int* idxp = g_idx + b * NN;
    while (mm) {
        int it = __ffs(mm) - 1;
        mm &= mm - 1;
        idxp[off++] = it * 512 + tid;
    }
    unsigned pad = ((tot + 63u) & ~63u) - tot;
    if ((unsigned)tid < pad) idxp[tot + tid] = NN;

    if (tid == 0) {
        g_cnt[b] = (int)tot;
#pragma unroll
        for (int q5 = 0; q5 < 5; q5++) {
            float s = 0.f;
#pragma unroll
            for (int ww = 0; ww < 16; ww++) s += wred[q5 * 16 + ww];
            g_scal[b * 8 + q5] = s;
        }
    }

    if (b < 16 && tid < 256) {
        int gi = b * 256 + tid;
        float s = 0.f;
#pragma unroll
        for (int p = 0; p < NGPART; p++) s += g_Gpart[p * KK * KK + gi];
        if ((gi >> 6) == (gi & 63)) s += 1.0f;
        g_G[gi] = s;
    }
}

// ---------------- kernel 3: partial U = dp @ Ct, grid (8 btiles, 64 chunks) --
__global__ void k_upart() {
    __shared__ float DPt[64 * DP_STRIDE];
    __shared__ float Cts[64 * CS_STRIDE];
    int tid = threadIdx.x;
    int btile = blockIdx.x * 32;   // gridDim.x = 8
    int nch = blockIdx.y;          // gridDim.y = 64
    int n0 = nch * 64;

    {
        int r2 = tid >> 2, q2 = tid & 3;
        const float4* cs = (const float4*)(g_Ct + (n0 + r2) * KK + q2 * 16);
#pragma unroll
        for (int i = 0; i < 4; i++)
            *(float4*)&Cts[r2 * CS_STRIDE + q2 * 16 + i * 4] = cs[i];
    }
    {
        int r = tid >> 3, q = tid & 7;
        const float4* ds = (const float4*)(g_dp + (btile + r) * NN + n0 + q * 8);
        float4 d0 = ds[0], d1 = ds[1];
        int nb0 = q * 8;
        DPt[(nb0 + 0) * DP_STRIDE + r] = d0.x;
        DPt[(nb0 + 1) * DP_STRIDE + r] = d0.y;
        DPt[(nb0 + 2) * DP_STRIDE + r] = d0.z;
        DPt[(nb0 + 3) * DP_STRIDE + r] = d0.w;
        DPt[(nb0 + 4) * DP_STRIDE + r] = d1.x;
        DPt[(nb0 + 5) * DP_STRIDE + r] = d1.y;
        DPt[(nb0 + 6) * DP_STRIDE + r] = d1.z;
        DPt[(nb0 + 7) * DP_STRIDE + r] = d1.w;
    }
    __syncthreads();

    int ty = tid >> 4, tx = tid & 15;
    unsigned long long acc2[4] = {0ull, 0ull, 0ull, 0ull};
#pragma unroll 16
    for (int s = 0; s < 64; s++) {
        unsigned long long a01 =
            *(const unsigned long long*)&DPt[s * DP_STRIDE + 2 * ty];
        float4 b4 = *(const float4*)&Cts[s * CS_STRIDE + tx * 4];
        fma2(acc2[0], a01, pack2(b4.x, b4.x));
        fma2(acc2[1], a01, pack2(b4.y, b4.y));
        fma2(acc2[2], a01, pack2(b4.z, b4.z));
        fma2(acc2[3], a01, pack2(b4.w, b4.w));
    }
    float* outp = g_Upart + nch * BB * KK;
#pragma unroll
    for (int j = 0; j < 4; j++) {
        float lo, hi;
        unpack2(acc2[j], lo, hi);
        outp[(btile + 2 * ty + 0) * KK + tx * 4 + j] = lo;
        outp[(btile + 2 * ty + 1) * KK + tx * 4 + j] = hi;
    }
}

// ---------------- kernel 4: partial correction SYRK, 2 CTAs per b ------------
// CTA (b, half) accumulates S over gather tiles t = half, half+2, ... and
// writes a partial 64x64 matrix. launch_bounds(256,3): 3 CTAs/SM residency
// to hide the LDS->FFMA dependency (R11 profile: issue 33% at 14 warps/SM).
__global__ void __launch_bounds__(256, 3) k_syrk() {
    __shared__ float Cs[64 * CS_STRIDE];
    int tid = threadIdx.x;
    int b = blockIdx.x >> 1;
    int half = blockIdx.x & 1;
    int ty = tid >> 4, tx = tid & 15;
    int r = tid >> 2, q = tid & 3;

    unsigned long long acc2[2][4];
#pragma unroll
    for (int ip = 0; ip < 2; ip++)
#pragma unroll
        for (int j = 0; j < 4; j++) acc2[ip][j] = 0ull;

    int cnt = g_cnt[b];
    int tiles = (cnt + 63) >> 6;
    const int* idxp = g_idx + b * NN;

    float4 pre[4];
    if (half < tiles) {
        int n = idxp[half * 64 + r];
        const float4* src = (const float4*)(g_Ct + n * KK + q * 16);
#pragma unroll
        for (int i = 0; i < 4; i++) pre[i] = src[i];
    }
    for (int t = half; t < tiles; t += 2) {
#pragma unroll
        for (int i = 0; i < 4; i++)
            *(float4*)&Cs[r * CS_STRIDE + q * 16 + i * 4] = pre[i];
        __syncthreads();
        if (t + 2 < tiles) {                  // register prefetch of next tile
            int n = idxp[(t + 2) * 64 + r];
            const float4* src = (const float4*)(g_Ct + n * KK + q * 16);
#pragma unroll
            for (int i = 0; i < 4; i++) pre[i] = src[i];
        }
#pragma unroll 16
        for (int s = 0; s < 64; s++) {
            ulonglong2 aa = *(const ulonglong2*)&Cs[s * CS_STRIDE + ty * 4];
            unsigned long long a01 = aa.x, a23 = aa.y;
            float4 b4 = *(const float4*)&Cs[s * CS_STRIDE + tx * 4];
            unsigned long long bd0 = pack2(b4.x, b4.x), bd1 = pack2(b4.y, b4.y);
            unsigned long long bd2 = pack2(b4.z, b4.z), bd3 = pack2(b4.w, b4.w);
            fma2(acc2[0][0], a01, bd0); fma2(acc2[0][1], a01, bd1);
            fma2(acc2[0][2], a01, bd2); fma2(acc2[0][3], a01, bd3);
            fma2(acc2[1][0], a23, bd0); fma2(acc2[1][1], a23, bd1);
            fma2(acc2[1][2], a23, bd2); fma2(acc2[1][3], a23, bd3);
        }
        __syncthreads();
    }

    float* outp = g_Spart + blockIdx.x * KK * KK;
#pragma unroll
    for (int ip = 0; ip < 2; ip++)
#pragma unroll
        for (int j = 0; j < 4; j++) {
            float lo, hi;
            unpack2(acc2[ip][j], lo, hi);
            outp[(ty * 4 + 2 * ip + 0) * KK + tx * 4 + j] = lo;
            outp[(ty * 4 + 2 * ip + 1) * KK + tx * 4 + j] = hi;
        }
}

// ---------------- kernel 5: As = G - S0 - S1, LDL^T, solve, assemble ---------
__global__ void __launch_bounds__(256, 2) k_fact(float* __restrict__ out) {
    __shared__ float As[64 * AS_STRIDE];
    __shared__ float ured[4][64];
    __shared__ float u_s[64], rinv_s[64], lred[2];
    __shared__ float zz_s;
    int b = blockIdx.x, tid = threadIdx.x;

    // parallel u-reduce: 64 partials split 4 ways across 256 threads
    {
        int kk = tid & 63, gg = tid >> 6;
        float s = 0.f;
#pragma unroll
        for (int p = 0; p < 16; p++)
            s += g_Upart[(gg * 16 + p) * BB * KK + b * KK + kk];
        ured[gg][kk] = s;
    }

    // As = G - S0 - S1 (coalesced)
    const float* s0 = g_Spart + (2 * b + 0) * KK * KK;
    const float* s1 = g_Spart + (2 * b + 1) * KK * KK;
#pragma unroll
    for (int i = tid; i < KK * KK; i += 256) {
        int row = i >> 6, col = i & 63;
        As[row * AS_STRIDE + col] = g_G[i] - s0[i] - s1[i];
    }
    __syncthreads();
    if (tid < 64)
        u_s[tid] = ured[0][tid] + ured[1][tid] + ured[2][tid] + ured[3][tid];
    __syncthreads();

    // ---- LDL^T factorization: one barrier per column ----
    int urow = tid >> 6;       // 0..3
    int ucol = tid & 63;       // 0..63
    for (int j = 0; j < 64; j++) {
        float rinv = 1.0f / As[j * AS_STRIDE + j];   // p_j stays at the diagonal
        if (tid == 0) rinv_s[j] = rinv;
        int cc = j + 1 + ucol;
        if (cc < 64) {
            float f = As[cc * AS_STRIDE + j] * rinv;
            for (int rr = j + 1 + urow; rr < 64; rr += 4)
                As[rr * AS_STRIDE + cc] -= As[rr * AS_STRIDE + j] * f;
        }
        __syncthreads();
    }

    // ---- forward solve on warp 0 (no block barriers) ----
    if (tid < 32) {
        float y0 = u_s[tid], y1 = u_s[tid + 32];
        float zz = 0.f;
        for (int j = 0; j < 64; j++) {
            float yj;
            if (j < 32) yj = __shfl_sync(0xffffffffu, y0, j);
            else        yj = __shfl_sync(0xffffffffu, y1, j - 32);
            float wv = yj * rinv_s[j];
            zz += yj * wv;
            if (tid > j)      y0 -= As[tid * AS_STRIDE + j] * wv;
            if (tid + 32 > j) y1 -= As[(tid + 32) * AS_STRIDE + j] * wv;
        }
        if (tid == 0) zz_s = zz;
    }

    // ---- parallel logdet from untouched diagonal p_j ----
    if (tid >= 64 && tid < 128) {
        int j = tid - 64;
        float lg = logf(As[j * AS_STRIDE + j]);
#pragma unroll
        for (int o = 16; o > 0; o >>= 1) lg += __shfl_xor_sync(0xffffffffu, lg, o);
        if ((j & 31) == 0) lred[j >> 5] = lg;
    }
    __syncthreads();

    if (tid == 0) {
        float uni   = g_scal[b * 8 + 0];
        float extra = g_scal[b * 8 + 1];
        float wd2   = g_scal[b * 8 + 2];
        float slp   = g_scal[b * 8 + 3];
        float nb    = g_scal[b * 8 + 4];
        float logdetA = lred[0] + lred[1];
        const float LOG2PI = 1.8378770664093453f;
        float gauss = -0.5f * (nb * LOG2PI + (slp + logdetA) + (wd2 - zz_s));
        out[b] = uni + gauss + extra;
    }
}

// ---------------- launch ------------------------------------------------------
extern "C" void kernel_launch(void* const* d_in, const int* in_sizes, int n_in,
                              void* d_out, int out_size) {
    const float* targets = (const float*)d_in[0];
    const float* rho     = (const float*)d_in[1];
    const float* qs      = (const float*)d_in[2];
    const float* means   = (const float*)d_in[3];
    const float* C       = (const float*)d_in[4];
    const float* psi     = (const float*)d_in[5];
    float* out = (float*)d_out;

    k_gprep<<<NGPART, 256>>>(C, psi);
    k_ew<<<BB, 512>>>(targets, rho, qs, means);
    k_upart<<<dim3(8, NUPART), 256>>>();
    k_syrk<<<BB * NSPLIT, 256>>>();
    k_fact<<<BB, 256>>>(out);
}

// round 15
// speedup vs baseline: 1.3723x; 1.0342x over previous
#include <cuda_runtime.h>
#include <math.h>

#define BB 256
#define NN 4096
#define KK 64
#define CS_STRIDE 68   // 64 + 4 pad; 272 bytes = 17*16, keeps 16B alignment
#define DP_STRIDE 34   // 32 + 2 pad; even => 8B-aligned LDS.64 rows
#define AS_STRIDE 65
#define NGPART 64      // Gram partial chunks (64 columns each)
#define NUPART 64      // U partial chunks (64 columns each)
#define NSPLIT 3       // SYRK partial split per batch row

// ---------------- packed f32x2 helpers (Blackwell full-rate fp32) ------------
__device__ __forceinline__ void fma2(unsigned long long& acc, unsigned long long a,
                                     unsigned long long b) {
    asm("fma.rn.f32x2 %0, %1, %2, %0;" : "+l"(acc) : "l"(a), "l"(b));
}
__device__ __forceinline__ unsigned long long pack2(float lo, float hi) {
    unsigned long long r;
    asm("mov.b64 %0, {%1, %2};" : "=l"(r) : "f"(lo), "f"(hi));
    return r;
}
__device__ __forceinline__ void unpack2(unsigned long long v, float& lo, float& hi) {
    asm("mov.b64 {%0, %1}, %2;" : "=f"(lo), "=f"(hi) : "l"(v));
}

// ---------------- scratch (static device globals; no allocation) -------------
__device__ float g_Ct[(NN + 1) * KK];        // C'[n][k]; extra zero row at n=NN
__device__ float g_rpsi[NN];                 // rsqrt(psi)
__device__ float g_lpsi[NN];                 // log(psi)
__device__ float g_Gpart[NGPART * KK * KK];  // partial Gram matrices
__device__ float g_G[KK * KK];               // I + C' C'^T
__device__ float g_dp[BB * NN];              // masked residual / sqrt(psi)
__device__ int   g_idx[BB * NN];             // compacted unmasked indices (padded)
__device__ int   g_cnt[BB];
__device__ float g_scal[BB * 8];             // per-row scalar reductions
__device__ float g_Upart[NUPART * BB * KK];  // partial u vectors
__device__ float g_Spart[NSPLIT * BB * KK * KK]; // partial correction SYRKs (12 MB)

// ---------------- kernel 1: FUSED scale+transpose+Gram-partial ---------------
__global__ void k_gprep(const float* __restrict__ C, const float* __restrict__ psi) {
    __shared__ float Cs[64 * CS_STRIDE];
    __shared__ float rps[64];
    int tid = threadIdx.x;
    int n0 = blockIdx.x * 64;      // grid = 64

    if (tid < 64) {
        float ps = psi[n0 + tid];
        float rp = rsqrtf(ps);
        rps[tid] = rp;
        g_rpsi[n0 + tid] = rp;
        g_lpsi[n0 + tid] = logf(ps);
    }
    __syncthreads();

    int k = tid & 63, ng = tid >> 6;
    float vals[16];
#pragma unroll
    for (int i = 0; i < 4; i++) {
        float4 c4 = *(const float4*)(C + k * NN + n0 + ng * 16 + i * 4);
        int nb = ng * 16 + i * 4;
        vals[i * 4 + 0] = c4.x * rps[nb + 0];
        vals[i * 4 + 1] = c4.y * rps[nb + 1];
        vals[i * 4 + 2] = c4.z * rps[nb + 2];
        vals[i * 4 + 3] = c4.w * rps[nb + 3];
    }
#pragma unroll
    for (int i = 0; i < 16; i++) {
        int n = ng * 16 + i;
        Cs[n * CS_STRIDE + k] = vals[i];
        g_Ct[(n0 + n) * KK + k] = vals[i];
    }
    __syncthreads();

    int ty = tid >> 4, tx = tid & 15;
    unsigned long long acc2[2][4];
#pragma unroll
    for (int ip = 0; ip < 2; ip++)
#pragma unroll
        for (int j = 0; j < 4; j++) acc2[ip][j] = 0ull;
#pragma unroll 16
    for (int s = 0; s < 64; s++) {
        ulonglong2 aa = *(const ulonglong2*)&Cs[s * CS_STRIDE + ty * 4];
        unsigned long long a01 = aa.x, a23 = aa.y;
        float4 b4 = *(const float4*)&Cs[s * CS_STRIDE + tx * 4];
        unsigned long long bd0 = pack2(b4.x, b4.x), bd1 = pack2(b4.y, b4.y);
        unsigned long long bd2 = pack2(b4.z, b4.z), bd3 = pack2(b4.w, b4.w);
        fma2(acc2[0][0], a01, bd0); fma2(acc2[0][1], a01, bd1);
        fma2(acc2[0][2], a01, bd2); fma2(acc2[0][3], a01, bd3);
        fma2(acc2[1][0], a23, bd0); fma2(acc2[1][1], a23, bd1);
        fma2(acc2[1][2], a23, bd2); fma2(acc2[1][3], a23, bd3);
    }
    float* out = g_Gpart + blockIdx.x * KK * KK;
#pragma unroll
    for (int ip = 0; ip < 2; ip++)
#pragma unroll
        for (int j = 0; j < 4; j++) {
            float lo, hi;
            unpack2(acc2[ip][j], lo, hi);
            out[(ty * 4 + 2 * ip + 0) * KK + tx * 4 + j] = lo;
            out[(ty * 4 + 2 * ip + 1) * KK + tx * 4 + j] = hi;
        }
}

// ---------------- kernel 2: elementwise + compaction (block = 512) -----------
__global__ void k_ew(const float* __restrict__ targets, const float* __restrict__ rho,
                     const float* __restrict__ qs, const float* __restrict__ means) {
    __shared__ unsigned warptot[16];
    __shared__ float wred[5 * 16];
    int b = blockIdx.x, tid = threadIdx.x;
    int lane = tid & 31, w = tid >> 5;
    float rho_s = rho[0];
    float logrho = logf(rho_s);
    const float* tg = targets + b * NN;
    const float* qp = qs + b * NN;
    const float* mp = means + b * NN;

    float uni = 0.f, extra = 0.f, wd2 = 0.f, slogpsi = 0.f, nb = 0.f;
    unsigned mask = 0;

#pragma unroll
    for (int it = 0; it < 8; it++) {
        int n = it * 512 + tid;
        float t = tg[n], qv = qp[n], mu = mp[n];
        bool masked = (t >= rho_s);
        float dpv = 0.0f;
        if (masked) {
            float lt = logf(t);
            dpv = (lt - mu) * g_rpsi[n];
            wd2 += dpv * dpv;
            slogpsi += g_lpsi[n];
            nb += 1.0f;
            extra += logf(qv) - lt;
        } else {
            uni += log1pf(-qv) - logrho;
            mask |= (1u << it);
        }
        g_dp[b * NN + n] = dpv;
    }

    unsigned cnt = __popc(mask);
    unsigned x = cnt;
#pragma unroll
    for (int o = 1; o < 32; o <<= 1) {
        unsigned y = __shfl_up_sync(0xffffffffu, x, o);
        if (lane >= o) x += y;
    }
    unsigned excl = x - cnt;
    if (lane == 31) warptot[w] = x;

    float vals[5] = {uni, extra, wd2, slogpsi, nb};
#pragma unroll
    for (int q5 = 0; q5 < 5; q5++) {
        float v = vals[q5];
#pragma unroll
        for (int off2 = 16; off2 > 0; off2 >>= 1) v += __shfl_xor_sync(0xffffffffu, v, off2);
        if (lane == 0) wred[q5 * 16 + w] = v;
    }
    __syncthreads();

    unsigned off = excl;
    for (int ww = 0; ww < w; ww++) off += warptot[ww];
    unsigned tot = 0;
#pragma unroll
    for (int ww = 0; ww < 16; ww++) tot += warptot[ww];

    unsigned mm = mask;
    int* idxp = g_idx + b * NN;
    while (mm) {
        int it = __ffs(mm) - 1;
        mm &= mm - 1;
        idxp[off++] = it * 512 + tid;
    }
    unsigned pad = ((tot + 63u) & ~63u) - tot;
    if ((unsigned)tid < pad) idxp[tot + tid] = NN;

    if (tid == 0) {
        g_cnt[b] = (int)tot;
#pragma unroll
        for (int q5 = 0; q5 < 5; q5++) {
            float s = 0.f;
#pragma unroll
            for (int ww = 0; ww < 16; ww++) s += wred[q5 * 16 + ww];
            g_scal[b * 8 + q5] = s;
        }
    }

    if (b < 16 && tid < 256) {
        int gi = b * 256 + tid;
        float s = 0.f;
#pragma unroll
        for (int p = 0; p < NGPART; p++) s += g_Gpart[p * KK * KK + gi];
        if ((gi >> 6) == (gi & 63)) s += 1.0f;
        g_G[gi] = s;
    }
}

// ---------------- kernel 3: partial U = dp @ Ct, grid (8 btiles, 64 chunks) --
__global__ void k_upart() {
    __shared__ float DPt[64 * DP_STRIDE];
    __shared__ float Cts[64 * CS_STRIDE];
    int tid = threadIdx.x;
    int btile = blockIdx.x * 32;   // gridDim.x = 8
    int nch = blockIdx.y;          // gridDim.y = 64
    int n0 = nch * 64;

    {
        int r2 = tid >> 2, q2 = tid & 3;
        const float4* cs = (const float4*)(g_Ct + (n0 + r2) * KK + q2 * 16);
#pragma unroll
        for (int i = 0; i < 4; i++)
            *(float4*)&Cts[r2 * CS_STRIDE + q2 * 16 + i * 4] = cs[i];
    }
    {
        int r = tid >> 3, q = tid & 7;
        const float4* ds = (const float4*)(g_dp + (btile + r) * NN + n0 + q * 8);
        float4 d0 = ds[0], d1 = ds[1];
        int nb0 = q * 8;
        DPt[(nb0 + 0) * DP_STRIDE + r] = d0.x;
        DPt[(nb0 + 1) * DP_STRIDE + r] = d0.y;
        DPt[(nb0 + 2) * DP_STRIDE + r] = d0.z;
        DPt[(nb0 + 3) * DP_STRIDE + r] = d0.w;
        DPt[(nb0 + 4) * DP_STRIDE + r] = d1.x;
        DPt[(nb0 + 5) * DP_STRIDE + r] = d1.y;
        DPt[(nb0 + 6) * DP_STRIDE + r] = d1.z;
        DPt[(nb0 + 7) * DP_STRIDE + r] = d1.w;
    }
    __syncthreads();

    int ty = tid >> 4, tx = tid & 15;
    unsigned long long acc2[4] = {0ull, 0ull, 0ull, 0ull};
#pragma unroll 16
    for (int s = 0; s < 64; s++) {
        unsigned long long a01 =
            *(const unsigned long long*)&DPt[s * DP_STRIDE + 2 * ty];
        float4 b4 = *(const float4*)&Cts[s * CS_STRIDE + tx * 4];
        fma2(acc2[0], a01, pack2(b4.x, b4.x));
        fma2(acc2[1], a01, pack2(b4.y, b4.y));
        fma2(acc2[2], a01, pack2(b4.z, b4.z));
        fma2(acc2[3], a01, pack2(b4.w, b4.w));
    }
    float* outp = g_Upart + nch * BB * KK;
#pragma unroll
    for (int j = 0; j < 4; j++) {
        float lo, hi;
        unpack2(acc2[j], lo, hi);
        outp[(btile + 2 * ty + 0) * KK + tx * 4 + j] = lo;
        outp[(btile + 2 * ty + 1) * KK + tx * 4 + j] = hi;
    }
}

// ---------------- kernel 4: partial correction SYRK, 3 CTAs per b ------------
// 128 threads, 8 rows x 4 cols per thread (2x arithmetic intensity vs 4x4:
// R12 profile showed L1/shared = 71% = crossbar-bound). Register-prefetch
// staging (proven in the 136.3us run) instead of cp.async to de-risk infra.
__global__ void __launch_bounds__(128, 4) k_syrk() {
    __shared__ float Cs[64 * CS_STRIDE];      // 17.4KB
    int tid = threadIdx.x;
    int b = blockIdx.x / NSPLIT;
    int part = blockIdx.x % NSPLIT;
    int ty = tid >> 4, tx = tid & 15;         // rows 8ty..8ty+7, cols 4tx..4tx+3
    int sr = tid >> 1, sq = tid & 1;          // staging: row sr, half-row sq (32 floats)

    unsigned long long acc2[4][4];
#pragma unroll
    for (int p = 0; p < 4; p++)
#pragma unroll
        for (int j = 0; j < 4; j++) acc2[p][j] = 0ull;

    int cnt = g_cnt[b];
    int tiles = (cnt + 63) >> 6;
    const int* idxp = g_idx + b * NN;

    float4 pre[8];
    if (part < tiles) {
        int n = idxp[part * 64 + sr];
        const float4* src = (const float4*)(g_Ct + n * KK + sq * 32);
#pragma unroll
        for (int i = 0; i < 8; i++) pre[i] = src[i];
    }
    for (int t = part; t < tiles; t += NSPLIT) {
#pragma unroll
        for (int i = 0; i < 8; i++)
            *(float4*)&Cs[sr * CS_STRIDE + sq * 32 + i * 4] = pre[i];
        __syncthreads();
        if (t + NSPLIT < tiles) {             // register prefetch of next tile
            int n = idxp[(t + NSPLIT) * 64 + sr];
            const float4* src = (const float4*)(g_Ct + n * KK + sq * 32);
#pragma unroll
            for (int i = 0; i < 8; i++) pre[i] = src[i];
        }
#pragma unroll 16
        for (int s = 0; s < 64; s++) {
            ulonglong2 aa = *(const ulonglong2*)&Cs[s * CS_STRIDE + ty * 8];
            ulonglong2 ab = *(const ulonglong2*)&Cs[s * CS_STRIDE + ty * 8 + 4];
            float4 b4 = *(const float4*)&Cs[s * CS_STRIDE + tx * 4];
            unsigned long long bd0 = pack2(b4.x, b4.x), bd1 = pack2(b4.y, b4.y);
            unsigned long long bd2 = pack2(b4.z, b4.z), bd3 = pack2(b4.w, b4.w);
            fma2(acc2[0][0], aa.x, bd0); fma2(acc2[0][1], aa.x, bd1);
            fma2(acc2[0][2], aa.x, bd2); fma2(acc2[0][3], aa.x, bd3);
            fma2(acc2[1][0], aa.y, bd0); fma2(acc2[1][1], aa.y, bd1);
            fma2(acc2[1][2], aa.y, bd2); fma2(acc2[1][3], aa.y, bd3);
            fma2(acc2[2][0], ab.x, bd0); fma2(acc2[2][1], ab.x, bd1);
            fma2(acc2[2][2], ab.x, bd2); fma2(acc2[2][3], ab.x, bd3);
            fma2(acc2[3][0], ab.y, bd0); fma2(acc2[3][1], ab.y, bd1);
            fma2(acc2[3][2], ab.y, bd2); fma2(acc2[3][3], ab.y, bd3);
        }
        __syncthreads();
    }

    float* outp = g_Spart + blockIdx.x * KK * KK;
#pragma unroll
    for (int p = 0; p < 4; p++)
#pragma unroll
        for (int j = 0; j < 4; j++) {
            float lo, hi;
            unpack2(acc2[p][j], lo, hi);
            outp[(ty * 8 + 2 * p + 0) * KK + tx * 4 + j] = lo;
            outp[(ty * 8 + 2 * p + 1) * KK + tx * 4 + j] = hi;
        }
}

// ---------------- kernel 5: As = G - S0 - S1 - S2, LDL^T, solve, assemble ----
__global__ void __launch_bounds__(256, 2) k_fact(float* __restrict__ out) {
    __shared__ float As[64 * AS_STRIDE];
    __shared__ float ured[4][64];
    __shared__ float u_s[64], rinv_s[64], lred[2];
    __shared__ float zz_s;
    int b = blockIdx.x, tid = threadIdx.x;

    // parallel u-reduce: 64 partials split 4 ways across 256 threads
    {
        int kk = tid & 63, gg = tid >> 6;
        float s = 0.f;
#pragma unroll
        for (int p = 0; p < 16; p++)
            s += g_Upart[(gg * 16 + p) * BB * KK + b * KK + kk];
        ured[gg][kk] = s;
    }

    // As = G - S0 - S1 - S2 (coalesced)
    const float* s0 = g_Spart + (NSPLIT * b + 0) * KK * KK;
    const float* s1 = g_Spart + (NSPLIT * b + 1) * KK * KK;
    const float* s2 = g_Spart + (NSPLIT * b + 2) * KK * KK;
#pragma unroll
    for (int i = tid; i < KK * KK; i += 256) {
        int row = i >> 6, col = i & 63;
        As[row * AS_STRIDE + col] = g_G[i] - s0[i] - s1[i] - s2[i];
    }
    __syncthreads();
    if (tid < 64)
        u_s[tid] = ured[0][tid] + ured[1][tid] + ured[2][tid] + ured[3][tid];
    __syncthreads();

    // ---- LDL^T factorization: one barrier per column ----
    int urow = tid >> 6;       // 0..3
    int ucol = tid & 63;       // 0..63
    for (int j = 0; j < 64; j++) {
        float rinv = 1.0f / As[j * AS_STRIDE + j];   // p_j stays at the diagonal
        if (tid == 0) rinv_s[j] = rinv;
        int cc = j + 1 + ucol;
        if (cc < 64) {
            float f = As[cc * AS_STRIDE + j] * rinv;
            for (int rr = j + 1 + urow; rr < 64; rr += 4)
                As[rr * AS_STRIDE + cc] -= As[rr * AS_STRIDE + j] * f;
        }
        __syncthreads();
    }

    // ---- forward solve on warp 0 (no block barriers) ----
    if (tid < 32) {
        float y0 = u_s[tid], y1 = u_s[tid + 32];
        float zz = 0.f;
        for (int j = 0; j < 64; j++) {
            float yj;
            if (j < 32) yj = __shfl_sync(0xffffffffu, y0, j);
            else        yj = __shfl_sync(0xffffffffu, y1, j - 32);
            float wv = yj * rinv_s[j];
            zz += yj * wv;
            if (tid > j)      y0 -= As[tid * AS_STRIDE + j] * wv;
            if (tid + 32 > j) y1 -= As[(tid + 32) * AS_STRIDE + j] * wv;
        }
        if (tid == 0) zz_s = zz;
    }

    // ---- parallel logdet from untouched diagonal p_j ----
    if (tid >= 64 && tid < 128) {
        int j = tid - 64;
        float lg = logf(As[j * AS_STRIDE + j]);
#pragma unroll
        for (int o = 16; o > 0; o >>= 1) lg += __shfl_xor_sync(0xffffffffu, lg, o);
        if ((j & 31) == 0) lred[j >> 5] = lg;
    }
    __syncthreads();

    if (tid == 0) {
        float uni   = g_scal[b * 8 + 0];
        float extra = g_scal[b * 8 + 1];
        float wd2   = g_scal[b * 8 + 2];
        float slp   = g_scal[b * 8 + 3];
        float nb    = g_scal[b * 8 + 4];
        float logdetA = lred[0] + lred[1];
        const float LOG2PI = 1.8378770664093453f;
        float gauss = -0.5f * (nb * LOG2PI + (slp + logdetA) + (wd2 - zz_s));
        out[b] = uni + gauss + extra;
    }
}

// ---------------- launch ------------------------------------------------------
extern "C" void kernel_launch(void* const* d_in, const int* in_sizes, int n_in,
                              void* d_out, int out_size) {
    const float* targets = (const float*)d_in[0];
    const float* rho     = (const float*)d_in[1];
    const float* qs      = (const float*)d_in[2];
    const float* means   = (const float*)d_in[3];
    const float* C       = (const float*)d_in[4];
    const float* psi     = (const float*)d_in[5];
    float* out = (float*)d_out;

    k_gprep<<<NGPART, 256>>>(C, psi);
    k_ew<<<BB, 512>>>(targets, rho, qs, means);
    k_upart<<<dim3(8, NUPART), 256>>>();
    k_syrk<<<BB * NSPLIT, 128>>>();
    k_fact<<<BB, 256>>>(out);
}

// round 16
// speedup vs baseline: 1.4655x; 1.0679x over previous
#include <cuda_runtime.h>
#include <math.h>

#define BB 256
#define NN 4096
#define KK 64
#define CS_STRIDE 68   // 64 + 4 pad; 272 bytes = 17*16, keeps 16B alignment
#define DP_STRIDE 34   // 32 + 2 pad; even => 8B-aligned LDS.64 rows
#define AS_STRIDE 65
#define NGPART 64      // Gram partial chunks (64 columns each)
#define NUPART 64      // U partial chunks (64 columns each)
#define NSPLIT 3       // SYRK partial split per batch row

// ---------------- packed f32x2 helpers (Blackwell full-rate fp32) ------------
__device__ __forceinline__ void fma2(unsigned long long& acc, unsigned long long a,
                                     unsigned long long b) {
    asm("fma.rn.f32x2 %0, %1, %2, %0;" : "+l"(acc) : "l"(a), "l"(b));
}
__device__ __forceinline__ unsigned long long pack2(float lo, float hi) {
    unsigned long long r;
    asm("mov.b64 %0, {%1, %2};" : "=l"(r) : "f"(lo), "f"(hi));
    return r;
}
__device__ __forceinline__ void unpack2(unsigned long long v, float& lo, float& hi) {
    asm("mov.b64 {%0, %1}, %2;" : "=f"(lo), "=f"(hi) : "l"(v));
}

// ---------------- scratch (static device globals; no allocation) -------------
__device__ float g_Ct[(NN + 1) * KK];        // C'[n][k]; extra zero row at n=NN
__device__ float g_rpsi[NN];                 // rsqrt(psi)
__device__ float g_lpsi[NN];                 // log(psi)
__device__ float g_Gpart[NGPART * KK * KK];  // partial Gram matrices
__device__ float g_G[KK * KK];               // I + C' C'^T
__device__ float g_dp[BB * NN];              // masked residual / sqrt(psi)
__device__ int   g_idx[BB * NN];             // compacted unmasked indices (padded)
__device__ int   g_cnt[BB];
__device__ float g_scal[BB * 8];             // per-row scalar reductions
__device__ float g_Upart[NUPART * BB * KK];  // partial u vectors
__device__ float g_Spart[NSPLIT * BB * KK * KK]; // partial SYRKs (lower tri valid)

// ---------------- kernel 1: FUSED scale+transpose+Gram-partial ---------------
__global__ void k_gprep(const float* __restrict__ C, const float* __restrict__ psi) {
    __shared__ float Cs[64 * CS_STRIDE];
    __shared__ float rps[64];
    int tid = threadIdx.x;
    int n0 = blockIdx.x * 64;      // grid = 64

    if (tid < 64) {
        float ps = psi[n0 + tid];
        float rp = rsqrtf(ps);
        rps[tid] = rp;
        g_rpsi[n0 + tid] = rp;
        g_lpsi[n0 + tid] = logf(ps);
    }
    __syncthreads();

    int k = tid & 63, ng = tid >> 6;
    float vals[16];
#pragma unroll
    for (int i = 0; i < 4; i++) {
        float4 c4 = *(const float4*)(C + k * NN + n0 + ng * 16 + i * 4);
        int nb = ng * 16 + i * 4;
        vals[i * 4 + 0] = c4.x * rps[nb + 0];
        vals[i * 4 + 1] = c4.y * rps[nb + 1];
        vals[i * 4 + 2] = c4.z * rps[nb + 2];
        vals[i * 4 + 3] = c4.w * rps[nb + 3];
    }
#pragma unroll
    for (int i = 0; i < 16; i++) {
        int n = ng * 16 + i;
        Cs[n * CS_STRIDE + k] = vals[i];
        g_Ct[(n0 + n) * KK + k] = vals[i];
    }
    __syncthreads();

    int ty = tid >> 4, tx = tid & 15;
    unsigned long long acc2[2][4];
#pragma unroll
    for (int ip = 0; ip < 2; ip++)
#pragma unroll
        for (int j = 0; j < 4; j++) acc2[ip][j] = 0ull;
#pragma unroll 16
    for (int s = 0; s < 64; s++) {
        ulonglong2 aa = *(const ulonglong2*)&Cs[s * CS_STRIDE + ty * 4];
        unsigned long long a01 = aa.x, a23 = aa.y;
        float4 b4 = *(const float4*)&Cs[s * CS_STRIDE + tx * 4];
        unsigned long long bd0 = pack2(b4.x, b4.x), bd1 = pack2(b4.y, b4.y);
        unsigned long long bd2 = pack2(b4.z, b4.z), bd3 = pack2(b4.w, b4.w);
        fma2(acc2[0][0], a01, bd0); fma2(acc2[0][1], a01, bd1);
        fma2(acc2[0][2], a01, bd2); fma2(acc2[0][3], a01, bd3);
        fma2(acc2[1][0], a23, bd0); fma2(acc2[1][1], a23, bd1);
        fma2(acc2[1][2], a23, bd2); fma2(acc2[1][3], a23, bd3);
    }
    float* out = g_Gpart + blockIdx.x * KK * KK;
#pragma unroll
    for (int ip = 0; ip < 2; ip++)
#pragma unroll
        for (int j = 0; j < 4; j++) {
            float lo, hi;
            unpack2(acc2[ip][j], lo, hi);
            out[(ty * 4 + 2 * ip + 0) * KK + tx * 4 + j] = lo;
            out[(ty * 4 + 2 * ip + 1) * KK + tx * 4 + j] = hi;
        }
}

// ---------------- kernel 2: elementwise + compaction (block = 512) -----------
__global__ void k_ew(const float* __restrict__ targets, const float* __restrict__ rho,
                     const float* __restrict__ qs, const float* __restrict__ means) {
    __shared__ unsigned warptot[16];
    __shared__ float wred[5 * 16];
    int b = blockIdx.x, tid = threadIdx.x;
    int lane = tid & 31, w = tid >> 5;
    float rho_s = rho[0];
    float logrho = logf(rho_s);
    const float* tg = targets + b * NN;
    const float* qp = qs + b * NN;
    const float* mp = means + b * NN;

    float uni = 0.f, extra = 0.f, wd2 = 0.f, slogpsi = 0.f, nb = 0.f;
    unsigned mask = 0;

#pragma unroll
    for (int it = 0; it < 8; it++) {
        int n = it * 512 + tid;
        float t = tg[n], qv = qp[n], mu = mp[n];
        bool masked = (t >= rho_s);
        float dpv = 0.0f;
        if (masked) {
            float lt = logf(t);
            dpv = (lt - mu) * g_rpsi[n];
            wd2 += dpv * dpv;
            slogpsi += g_lpsi[n];
            nb += 1.0f;
            extra += logf(qv) - lt;
        } else {
            uni += log1pf(-qv) - logrho;
            mask |= (1u << it);
        }
        g_dp[b * NN + n] = dpv;
    }

    unsigned cnt = __popc(mask);
    unsigned x = cnt;
#pragma unroll
    for (int o = 1; o < 32; o <<= 1) {
        unsigned y = __shfl_up_sync(0xffffffffu, x, o);
        if (lane >= o) x += y;
    }
    unsigned excl = x - cnt;
    if (lane == 31) warptot[w] = x;

    float vals[5] = {uni, extra, wd2, slogpsi, nb};
#pragma unroll
    for (int q5 = 0; q5 < 5; q5++) {
        float v = vals[q5];
#pragma unroll
        for (int off2 = 16; off2 > 0; off2 >>= 1) v += __shfl_xor_sync(0xffffffffu, v, off2);
        if (lane == 0) wred[q5 * 16 + w] = v;
    }
    __syncthreads();

    unsigned off = excl;
    for (int ww = 0; ww < w; ww++) off += warptot[ww];
    unsigned tot = 0;
#pragma unroll
    for (int ww = 0; ww < 16; ww++) tot += warptot[ww];

    unsigned mm = mask;
    int* idxp = g_idx + b * NN;
    while (mm) {
        int it = __ffs(mm) - 1;
        mm &= mm - 1;
        idxp[off++] = it * 512 + tid;
    }
    unsigned pad = ((tot + 63u) & ~63u) - tot;
    if ((unsigned)tid < pad) idxp[tot + tid] = NN;

    if (tid == 0) {
        g_cnt[b] = (int)tot;
#pragma unroll
        for (int q5 = 0; q5 < 5; q5++) {
            float s = 0.f;
#pragma unroll
            for (int ww = 0; ww < 16; ww++) s += wred[q5 * 16 + ww];
            g_scal[b * 8 + q5] = s;
        }
    }

    if (b < 16 && tid < 256) {
        int gi = b * 256 + tid;
        float s = 0.f;
#pragma unroll
        for (int p = 0; p < NGPART; p++) s += g_Gpart[p * KK * KK + gi];
        if ((gi >> 6) == (gi & 63)) s += 1.0f;
        g_G[gi] = s;
    }
}

// ---------------- kernel 3: partial U = dp @ Ct, grid (8 btiles, 64 chunks) --
__global__ void k_upart() {
    __shared__ float DPt[64 * DP_STRIDE];
    __shared__ float Cts[64 * CS_STRIDE];
    int tid = threadIdx.x;
    int btile = blockIdx.x * 32;   // gridDim.x = 8
    int nch = blockIdx.y;          // gridDim.y = 64
    int n0 = nch * 64;

    {
        int r2 = tid >> 2, q2 = tid & 3;
        const float4* cs = (const float4*)(g_Ct + (n0 + r2) * KK + q2 * 16);
#pragma unroll
        for (int i = 0; i < 4; i++)
            *(float4*)&Cts[r2 * CS_STRIDE + q2 * 16 + i * 4] = cs[i];
    }
    {
        int r = tid >> 3, q = tid & 7;
        const float4* ds = (const float4*)(g_dp + (btile + r) * NN + n0 + q * 8);
        float4 d0 = ds[0], d1 = ds[1];
        int nb0 = q * 8;
        DPt[(nb0 + 0) * DP_STRIDE + r] = d0.x;
        DPt[(nb0 + 1) * DP_STRIDE + r] = d0.y;
        DPt[(nb0 + 2) * DP_STRIDE + r] = d0.z;
        DPt[(nb0 + 3) * DP_STRIDE + r] = d0.w;
        DPt[(nb0 + 4) * DP_STRIDE + r] = d1.x;
        DPt[(nb0 + 5) * DP_STRIDE + r] = d1.y;
        DPt[(nb0 + 6) * DP_STRIDE + r] = d1.z;
        DPt[(nb0 + 7) * DP_STRIDE + r] = d1.w;
    }
    __syncthreads();

    int ty = tid >> 4, tx = tid & 15;
    unsigned long long acc2[4] = {0ull, 0ull, 0ull, 0ull};
#pragma unroll 16
    for (int s = 0; s < 64; s++) {
        unsigned long long a01 =
            *(const unsigned long long*)&DPt[s * DP_STRIDE + 2 * ty];
        float4 b4 = *(const float4*)&Cts[s * CS_STRIDE + tx * 4];
        fma2(acc2[0], a01, pack2(b4.x, b4.x));
        fma2(acc2[1], a01, pack2(b4.y, b4.y));
        fma2(acc2[2], a01, pack2(b4.z, b4.z));
        fma2(acc2[3], a01, pack2(b4.w, b4.w));
    }
    float* outp = g_Upart + nch * BB * KK;
#pragma unroll
    for (int j = 0; j < 4; j++) {
        float lo, hi;
        unpack2(acc2[j], lo, hi);
        outp[(btile + 2 * ty + 0) * KK + tx * 4 + j] = lo;
        outp[(btile + 2 * ty + 1) * KK + tx * 4 + j] = hi;
    }
}

// ---------------- kernel 4: partial SYRK, lower triangle only ----------------
// S is symmetric: only the 72 of 128 8x4 blocks touching the lower triangle
// are computed (threads 72..127 stage + barrier only). Cuts FMA2 volume and
// b-column crossbar traffic to 56% -- attacks both walls at once.
__global__ void __launch_bounds__(128, 4) k_syrk() {
    __shared__ float Cs[64 * CS_STRIDE];      // 17.4KB
    int tid = threadIdx.x;
    int b = blockIdx.x / NSPLIT;
    int part = blockIdx.x % NSPLIT;
    int sr = tid >> 1, sq = tid & 1;          // staging: row sr, half-row sq

    // triangle block mapping: thread t<72 -> (ty,tx), tx <= 2ty+1
    bool active = (tid < 72);
    int ty = 0, tx = 0;
    if (active) {
        ty = (int)((sqrtf(4.0f * tid + 1.0f) - 1.0f) * 0.5f);
        while ((ty + 1) * (ty + 2) <= tid) ty++;
        while (ty * (ty + 1) > tid) ty--;
        tx = tid - ty * (ty + 1);
    }

    unsigned long long acc2[4][4];
#pragma unroll
    for (int p = 0; p < 4; p++)
#pragma unroll
        for (int j = 0; j < 4; j++) acc2[p][j] = 0ull;

    int cnt = g_cnt[b];
    int tiles = (cnt + 63) >> 6;
    const int* idxp = g_idx + b * NN;

    float4 pre[8];
    if (part < tiles) {
        int n = idxp[part * 64 + sr];
        const float4* src = (const float4*)(g_Ct + n * KK + sq * 32);
#pragma unroll
        for (int i = 0; i < 8; i++) pre[i] = src[i];
    }
    for (int t = part; t < tiles; t += NSPLIT) {
#pragma unroll
        for (int i = 0; i < 8; i++)
            *(float4*)&Cs[sr * CS_STRIDE + sq * 32 + i * 4] = pre[i];
        __syncthreads();
        if (t + NSPLIT < tiles) {             // register prefetch of next tile
            int n = idxp[(t + NSPLIT) * 64 + sr];
            const float4* src = (const float4*)(g_Ct + n * KK + sq * 32);
#pragma unroll
            for (int i = 0; i < 8; i++) pre[i] = src[i];
        }
        if (active) {
#pragma unroll 16
            for (int s = 0; s < 64; s++) {
                ulonglong2 aa = *(const ulonglong2*)&Cs[s * CS_STRIDE + ty * 8];
                ulonglong2 ab = *(const ulonglong2*)&Cs[s * CS_STRIDE + ty * 8 + 4];
                float4 b4 = *(const float4*)&Cs[s * CS_STRIDE + tx * 4];
                unsigned long long bd0 = pack2(b4.x, b4.x), bd1 = pack2(b4.y, b4.y);
                unsigned long long bd2 = pack2(b4.z, b4.z), bd3 = pack2(b4.w, b4.w);
                fma2(acc2[0][0], aa.x, bd0); fma2(acc2[0][1], aa.x, bd1);
                fma2(acc2[0][2], aa.x, bd2); fma2(acc2[0][3], aa.x, bd3);
                fma2(acc2[1][0], aa.y, bd0); fma2(acc2[1][1], aa.y, bd1);
                fma2(acc2[1][2], aa.y, bd2); fma2(acc2[1][3], aa.y, bd3);
                fma2(acc2[2][0], ab.x, bd0); fma2(acc2[2][1], ab.x, bd1);
                fma2(acc2[2][2], ab.x, bd2); fma2(acc2[2][3], ab.x, bd3);
                fma2(acc2[3][0], ab.y, bd0); fma2(acc2[3][1], ab.y, bd1);
                fma2(acc2[3][2], ab.y, bd2); fma2(acc2[3][3], ab.y, bd3);
            }
        }
        __syncthreads();
    }

    if (active) {
        float* outp = g_Spart + blockIdx.x * KK * KK;
#pragma unroll
        for (int p = 0; p < 4; p++)
#pragma unroll
            for (int j = 0; j < 4; j++) {
                float lo, hi;
                unpack2(acc2[p][j], lo, hi);
                outp[(ty * 8 + 2 * p + 0) * KK + tx * 4 + j] = lo;
                outp[(ty * 8 + 2 * p + 1) * KK + tx * 4 + j] = hi;
            }
    }
}

// ---------------- kernel 5: lower-tri As = G - S, LDL^T, solve, assemble -----
__global__ void __launch_bounds__(256, 2) k_fact(float* __restrict__ out) {
    __shared__ float As[64 * AS_STRIDE];
    __shared__ float ured[4][64];
    __shared__ float u_s[64], rinv_s[64], lred[2];
    __shared__ float zz_s;
    int b = blockIdx.x, tid = threadIdx.x;

    // parallel u-reduce: 64 partials split 4 ways across 256 threads
    {
        int kk = tid & 63, gg = tid >> 6;
        float s = 0.f;
#pragma unroll
        for (int p = 0; p < 16; p++)
            s += g_Upart[(gg * 16 + p) * BB * KK + b * KK + kk];
        ured[gg][kk] = s;
    }

    // As(lower) = G - S0 - S1 - S2 (upper triangle left untouched/garbage)
    const float* s0 = g_Spart + (NSPLIT * b + 0) * KK * KK;
    const float* s1 = g_Spart + (NSPLIT * b + 1) * KK * KK;
    const float* s2 = g_Spart + (NSPLIT * b + 2) * KK * KK;
#pragma unroll
    for (int i = tid; i < KK * KK; i += 256) {
        int row = i >> 6, col = i & 63;
        if (row >= col)
            As[row * AS_STRIDE + col] = g_G[i] - s0[i] - s1[i] - s2[i];
    }
    __syncthreads();
    if (tid < 64)
        u_s[tid] = ured[0][tid] + ured[1][tid] + ured[2][tid] + ured[3][tid];
    __syncthreads();

    // ---- LDL^T factorization on the lower triangle: one barrier per column --
    int urow = tid >> 6;       // 0..3
    int ucol = tid & 63;       // 0..63
    for (int j = 0; j < 64; j++) {
        float rinv = 1.0f / As[j * AS_STRIDE + j];   // p_j stays at the diagonal
        if (tid == 0) rinv_s[j] = rinv;
        int cc = j + 1 + ucol;
        if (cc < 64) {
            float f = As[cc * AS_STRIDE + j] * rinv;
            for (int rr = j + 1 + urow; rr < 64; rr += 4)
                if (rr >= cc)
                    As[rr * AS_STRIDE + cc] -= As[rr * AS_STRIDE + j] * f;
        }
        __syncthreads();
    }

    // ---- forward solve on warp 0 (reads lower triangle only) ----
    if (tid < 32) {
        float y0 = u_s[tid], y1 = u_s[tid + 32];
        float zz = 0.f;
        for (int j = 0; j < 64; j++) {
            float yj;
            if (j < 32) yj = __shfl_sync(0xffffffffu, y0, j);
            else        yj = __shfl_sync(0xffffffffu, y1, j - 32);
            float wv = yj * rinv_s[j];
            zz += yj * wv;
            if (tid > j)      y0 -= As[tid * AS_STRIDE + j] * wv;
            if (tid + 32 > j) y1 -= As[(tid + 32) * AS_STRIDE + j] * wv;
        }
        if (tid == 0) zz_s = zz;
    }

    // ---- parallel logdet from untouched diagonal p_j ----
    if (tid >= 64 && tid < 128) {
        int j = tid - 64;
        float lg = logf(As[j * AS_STRIDE + j]);
#pragma unroll
        for (int o = 16; o > 0; o >>= 1) lg += __shfl_xor_sync(0xffffffffu, lg, o);
        if ((j & 31) == 0) lred[j >> 5] = lg;
    }
    __syncthreads();

    if (tid == 0) {
        float uni   = g_scal[b * 8 + 0];
        float extra = g_scal[b * 8 + 1];
        float wd2   = g_scal[b * 8 + 2];
        float slp   = g_scal[b * 8 + 3];
        float nb    = g_scal[b * 8 + 4];
        float logdetA = lred[0] + lred[1];
        const float LOG2PI = 1.8378770664093453f;
        float gauss = -0.5f * (nb * LOG2PI + (slp + logdetA) + (wd2 - zz_s));
        out[b] = uni + gauss + extra;
    }
}

// ---------------- launch ------------------------------------------------------
extern "C" void kernel_launch(void* const* d_in, const int* in_sizes, int n_in,
                              void* d_out, int out_size) {
    const float* targets = (const float*)d_in[0];
    const float* rho     = (const float*)d_in[1];
    const float* qs      = (const float*)d_in[2];
    const float* means   = (const float*)d_in[3];
    const float* C       = (const float*)d_in[4];
    const float* psi     = (const float*)d_in[5];
    float* out = (float*)d_out;

    k_gprep<<<NGPART, 256>>>(C, psi);
    k_ew<<<BB, 512>>>(targets, rho, qs, means);
    k_upart<<<dim3(8, NUPART), 256>>>();
    k_syrk<<<BB * NSPLIT, 128>>>();
    k_fact<<<BB, 256>>>(out);
}

// round 17
// speedup vs baseline: 1.4708x; 1.0036x over previous
#include <cuda_runtime.h>
#include <math.h>

#define BB 256
#define NN 4096
#define KK 64
#define CS_STRIDE 68   // 64 + 4 pad; 272 bytes = 17*16, keeps 16B alignment
#define DP_STRIDE 34   // 32 + 2 pad; even => 8B-aligned LDS.64 rows
#define AS_STRIDE 65
#define NGPART 64      // Gram partial chunks (64 columns each)
#define NUPART 64      // U partial chunks (64 columns each)
#define NSPLIT 3       // SYRK partial split per batch row

// ---------------- packed f32x2 helpers (Blackwell full-rate fp32) ------------
__device__ __forceinline__ void fma2(unsigned long long& acc, unsigned long long a,
                                     unsigned long long b) {
    asm("fma.rn.f32x2 %0, %1, %2, %0;" : "+l"(acc) : "l"(a), "l"(b));
}
__device__ __forceinline__ unsigned long long pack2(float lo, float hi) {
    unsigned long long r;
    asm("mov.b64 %0, {%1, %2};" : "=l"(r) : "f"(lo), "f"(hi));
    return r;
}
__device__ __forceinline__ void unpack2(unsigned long long v, float& lo, float& hi) {
    asm("mov.b64 {%0, %1}, %2;" : "=f"(lo), "=f"(hi) : "l"(v));
}

// ---------------- scratch (static device globals; no allocation) -------------
__device__ float g_Ct[(NN + 1) * KK];        // C'[n][k]; extra zero row at n=NN
__device__ float g_rpsi[NN];                 // rsqrt(psi)
__device__ float g_lpsi[NN];                 // log(psi)
__device__ float g_Gpart[NGPART * KK * KK];  // partial Gram matrices
__device__ float g_G[KK * KK];               // I + C' C'^T
__device__ float g_dp[BB * NN];              // masked residual / sqrt(psi)
__device__ int   g_idx[BB * NN];             // compacted unmasked indices (padded)
__device__ int   g_cnt[BB];
__device__ float g_scal[BB * 8];             // per-row scalar reductions
__device__ float g_Upart[NUPART * BB * KK];  // partial u vectors
__device__ float g_Spart[NSPLIT * BB * KK * KK]; // partial SYRKs (lower tri valid)

// ---------------- kernel 1: FUSED scale+transpose+Gram-partial ---------------
__global__ void k_gprep(const float* __restrict__ C, const float* __restrict__ psi) {
    __shared__ float Cs[64 * CS_STRIDE];
    __shared__ float rps[64];
    int tid = threadIdx.x;
    int n0 = blockIdx.x * 64;      // grid = 64

    if (tid < 64) {
        float ps = psi[n0 + tid];
        float rp = rsqrtf(ps);
        rps[tid] = rp;
        g_rpsi[n0 + tid] = rp;
        g_lpsi[n0 + tid] = logf(ps);
    }
    __syncthreads();

    int k = tid & 63, ng = tid >> 6;
    float vals[16];
#pragma unroll
    for (int i = 0; i < 4; i++) {
        float4 c4 = *(const float4*)(C + k * NN + n0 + ng * 16 + i * 4);
        int nb = ng * 16 + i * 4;
        vals[i * 4 + 0] = c4.x * rps[nb + 0];
        vals[i * 4 + 1] = c4.y * rps[nb + 1];
        vals[i * 4 + 2] = c4.z * rps[nb + 2];
        vals[i * 4 + 3] = c4.w * rps[nb + 3];
    }
#pragma unroll
    for (int i = 0; i < 16; i++) {
        int n = ng * 16 + i;
        Cs[n * CS_STRIDE + k] = vals[i];
        g_Ct[(n0 + n) * KK + k] = vals[i];
    }
    __syncthreads();

    int ty = tid >> 4, tx = tid & 15;
    unsigned long long acc2[2][4];
#pragma unroll
    for (int ip = 0; ip < 2; ip++)
#pragma unroll
        for (int j = 0; j < 4; j++) acc2[ip][j] = 0ull;
#pragma unroll 16
    for (int s = 0; s < 64; s++) {
        ulonglong2 aa = *(const ulonglong2*)&Cs[s * CS_STRIDE + ty * 4];
        unsigned long long a01 = aa.x, a23 = aa.y;
        float4 b4 = *(const float4*)&Cs[s * CS_STRIDE + tx * 4];
        unsigned long long bd0 = pack2(b4.x, b4.x), bd1 = pack2(b4.y, b4.y);
        unsigned long long bd2 = pack2(b4.z, b4.z), bd3 = pack2(b4.w, b4.w);
        fma2(acc2[0][0], a01, bd0); fma2(acc2[0][1], a01, bd1);
        fma2(acc2[0][2], a01, bd2); fma2(acc2[0][3], a01, bd3);
        fma2(acc2[1][0], a23, bd0); fma2(acc2[1][1], a23, bd1);
        fma2(acc2[1][2], a23, bd2); fma2(acc2[1][3], a23, bd3);
    }
    float* out = g_Gpart + blockIdx.x * KK * KK;
#pragma unroll
    for (int ip = 0; ip < 2; ip++)
#pragma unroll
        for (int j = 0; j < 4; j++) {
            float lo, hi;
            unpack2(acc2[ip][j], lo, hi);
            out[(ty * 4 + 2 * ip + 0) * KK + tx * 4 + j] = lo;
            out[(ty * 4 + 2 * ip + 1) * KK + tx * 4 + j] = hi;
        }
}

// ---------------- kernel 2: elementwise + compaction (block = 512) -----------
__global__ void k_ew(const float* __restrict__ targets, const float* __restrict__ rho,
                     const float* __restrict__ qs, const float* __restrict__ means) {
    __shared__ unsigned warptot[16];
    __shared__ float wred[5 * 16];
    int b = blockIdx.x, tid = threadIdx.x;
    int lane = tid & 31, w = tid >> 5;
    float rho_s = rho[0];
    float logrho = logf(rho_s);
    const float* tg = targets + b * NN;
    const float* qp = qs + b * NN;
    const float* mp = means + b * NN;

    float uni = 0.f, extra = 0.f, wd2 = 0.f, slogpsi = 0.f, nb = 0.f;
    unsigned mask = 0;

#pragma unroll
    for (int it = 0; it < 8; it++) {
        int n = it * 512 + tid;
        float t = tg[n], qv = qp[n], mu = mp[n];
        bool masked = (t >= rho_s);
        float dpv = 0.0f;
        if (masked) {
            float lt = logf(t);
            dpv = (lt - mu) * g_rpsi[n];
            wd2 += dpv * dpv;
            slogpsi += g_lpsi[n];
            nb += 1.0f;
            extra += logf(qv) - lt;
        } else {
            uni += log1pf(-qv) - logrho;
            mask |= (1u << it);
        }
        g_dp[b * NN + n] = dpv;
    }

    unsigned cnt = __popc(mask);
    unsigned x = cnt;
#pragma unroll
    for (int o = 1; o < 32; o <<= 1) {
        unsigned y = __shfl_up_sync(0xffffffffu, x, o);
        if (lane >= o) x += y;
    }
    unsigned excl = x - cnt;
    if (lane == 31) warptot[w] = x;

    float vals[5] = {uni, extra, wd2, slogpsi, nb};
#pragma unroll
    for (int q5 = 0; q5 < 5; q5++) {
        float v = vals[q5];
#pragma unroll
        for (int off2 = 16; off2 > 0; off2 >>= 1) v += __shfl_xor_sync(0xffffffffu, v, off2);
        if (lane == 0) wred[q5 * 16 + w] = v;
    }
    __syncthreads();

    unsigned off = excl;
    for (int ww = 0; ww < w; ww++) off += warptot[ww];
    unsigned tot = 0;
#pragma unroll
    for (int ww = 0; ww < 16; ww++) tot += warptot[ww];

    unsigned mm = mask;
    int* idxp = g_idx + b * NN;
    while (mm) {
        int it = __ffs(mm) - 1;
        mm &= mm - 1;
        idxp[off++] = it * 512 + tid;
    }
    unsigned pad = ((tot + 63u) & ~63u) - tot;
    if ((unsigned)tid < pad) idxp[tot + tid] = NN;

    if (tid == 0) {
        g_cnt[b] = (int)tot;
#pragma unroll
        for (int q5 = 0; q5 < 5; q5++) {
            float s = 0.f;
#pragma unroll
            for (int ww = 0; ww < 16; ww++) s += wred[q5 * 16 + ww];
            g_scal[b * 8 + q5] = s;
        }
    }

    if (b < 16 && tid < 256) {
        int gi = b * 256 + tid;
        float s = 0.f;
#pragma unroll
        for (int p = 0; p < NGPART; p++) s += g_Gpart[p * KK * KK + gi];
        if ((gi >> 6) == (gi & 63)) s += 1.0f;
        g_G[gi] = s;
    }
}

// ---------------- kernel 3: partial U = dp @ Ct, grid (8 btiles, 64 chunks) --
__global__ void k_upart() {
    __shared__ float DPt[64 * DP_STRIDE];
    __shared__ float Cts[64 * CS_STRIDE];
    int tid = threadIdx.x;
    int btile = blockIdx.x * 32;   // gridDim.x = 8
    int nch = blockIdx.y;          // gridDim.y = 64
    int n0 = nch * 64;

    {
        int r2 = tid >> 2, q2 = tid & 3;
        const float4* cs = (const float4*)(g_Ct + (n0 + r2) * KK + q2 * 16);
#pragma unroll
        for (int i = 0; i < 4; i++)
            *(float4*)&Cts[r2 * CS_STRIDE + q2 * 16 + i * 4] = cs[i];
    }
    {
        int r = tid >> 3, q = tid & 7;
        const float4* ds = (const float4*)(g_dp + (btile + r) * NN + n0 + q * 8);
        float4 d0 = ds[0], d1 = ds[1];
        int nb0 = q * 8;
        DPt[(nb0 + 0) * DP_STRIDE + r] = d0.x;
        DPt[(nb0 + 1) * DP_STRIDE + r] = d0.y;
        DPt[(nb0 + 2) * DP_STRIDE + r] = d0.z;
        DPt[(nb0 + 3) * DP_STRIDE + r] = d0.w;
        DPt[(nb0 + 4) * DP_STRIDE + r] = d1.x;
        DPt[(nb0 + 5) * DP_STRIDE + r] = d1.y;
        DPt[(nb0 + 6) * DP_STRIDE + r] = d1.z;
        DPt[(nb0 + 7) * DP_STRIDE + r] = d1.w;
    }
    __syncthreads();

    int ty = tid >> 4, tx = tid & 15;
    unsigned long long acc2[4] = {0ull, 0ull, 0ull, 0ull};
#pragma unroll 16
    for (int s = 0; s < 64; s++) {
        unsigned long long a01 =
            *(const unsigned long long*)&DPt[s * DP_STRIDE + 2 * ty];
        float4 b4 = *(const float4*)&Cts[s * CS_STRIDE + tx * 4];
        fma2(acc2[0], a01, pack2(b4.x, b4.x));
        fma2(acc2[1], a01, pack2(b4.y, b4.y));
        fma2(acc2[2], a01, pack2(b4.z, b4.z));
        fma2(acc2[3], a01, pack2(b4.w, b4.w));
    }
    float* outp = g_Upart + nch * BB * KK;
#pragma unroll
    for (int j = 0; j < 4; j++) {
        float lo, hi;
        unpack2(acc2[j], lo, hi);
        outp[(btile + 2 * ty + 0) * KK + tx * 4 + j] = lo;
        outp[(btile + 2 * ty + 1) * KK + tx * 4 + j] = hi;
    }
}

// ---------------- kernel 4: partial SYRK, lower triangle only ----------------
// S is symmetric: only the 72 of 128 8x4 blocks touching the lower triangle
// are computed (threads 72..127 stage + barrier only). Cuts FMA2 volume and
// b-column crossbar traffic to 56% -- attacks both walls at once.
__global__ void __launch_bounds__(128, 4) k_syrk() {
    __shared__ float Cs[64 * CS_STRIDE];      // 17.4KB
    int tid = threadIdx.x;
    int b = blockIdx.x / NSPLIT;
    int part = blockIdx.x % NSPLIT;
    int sr = tid >> 1, sq = tid & 1;          // staging: row sr, half-row sq

    // triangle block mapping: thread t<72 -> (ty,tx), tx <= 2ty+1
    bool active = (tid < 72);
    int ty = 0, tx = 0;
    if (active) {
        ty = (int)((sqrtf(4.0f * tid + 1.0f) - 1.0f) * 0.5f);
        while ((ty + 1) * (ty + 2) <= tid) ty++;
        while (ty * (ty + 1) > tid) ty--;
        tx = tid - ty * (ty + 1);
    }

    unsigned long long acc2[4][4];
#pragma unroll
    for (int p = 0; p < 4; p++)
#pragma unroll
        for (int j = 0; j < 4; j++) acc2[p][j] = 0ull;

    int cnt = g_cnt[b];
    int tiles = (cnt + 63) >> 6;
    const int* idxp = g_idx + b * NN;

    float4 pre[8];
    if (part < tiles) {
        int n = idxp[part * 64 + sr];
        const float4* src = (const float4*)(g_Ct + n * KK + sq * 32);
#pragma unroll
        for (int i = 0; i < 8; i++) pre[i] = src[i];
    }
    for (int t = part; t < tiles; t += NSPLIT) {
#pragma unroll
        for (int i = 0; i < 8; i++)
            *(float4*)&Cs[sr * CS_STRIDE + sq * 32 + i * 4] = pre[i];
        __syncthreads();
        if (t + NSPLIT < tiles) {             // register prefetch of next tile
            int n = idxp[(t + NSPLIT) * 64 + sr];
            const float4* src = (const float4*)(g_Ct + n * KK + sq * 32);
#pragma unroll
            for (int i = 0; i < 8; i++) pre[i] = src[i];
        }
        if (active) {
#pragma unroll 16
            for (int s = 0; s < 64; s++) {
                ulonglong2 aa = *(const ulonglong2*)&Cs[s * CS_STRIDE + ty * 8];
                ulonglong2 ab = *(const ulonglong2*)&Cs[s * CS_STRIDE + ty * 8 + 4];
                float4 b4 = *(const float4*)&Cs[s * CS_STRIDE + tx * 4];
                unsigned long long bd0 = pack2(b4.x, b4.x), bd1 = pack2(b4.y, b4.y);
                unsigned long long bd2 = pack2(b4.z, b4.z), bd3 = pack2(b4.w, b4.w);
                fma2(acc2[0][0], aa.x, bd0); fma2(acc2[0][1], aa.x, bd1);
                fma2(acc2[0][2], aa.x, bd2); fma2(acc2[0][3], aa.x, bd3);
                fma2(acc2[1][0], aa.y, bd0); fma2(acc2[1][1], aa.y, bd1);
                fma2(acc2[1][2], aa.y, bd2); fma2(acc2[1][3], aa.y, bd3);
                fma2(acc2[2][0], ab.x, bd0); fma2(acc2[2][1], ab.x, bd1);
                fma2(acc2[2][2], ab.x, bd2); fma2(acc2[2][3], ab.x, bd3);
                fma2(acc2[3][0], ab.y, bd0); fma2(acc2[3][1], ab.y, bd1);
                fma2(acc2[3][2], ab.y, bd2); fma2(acc2[3][3], ab.y, bd3);
            }
        }
        __syncthreads();
    }

    if (active) {
        float* outp = g_Spart + blockIdx.x * KK * KK;
#pragma unroll
        for (int p = 0; p < 4; p++)
#pragma unroll
            for (int j = 0; j < 4; j++) {
                float lo, hi;
                unpack2(acc2[p][j], lo, hi);
                outp[(ty * 8 + 2 * p + 0) * KK + tx * 4 + j] = lo;
                outp[(ty * 8 + 2 * p + 1) * KK + tx * 4 + j] = hi;
            }
    }
}

// ---------------- kernel 5: lower-tri As = G - S, LDL^T, solve, assemble -----
__global__ void __launch_bounds__(256, 2) k_fact(float* __restrict__ out) {
    __shared__ float As[64 * AS_STRIDE];
    __shared__ float ured[4][64];
    __shared__ float u_s[64], rinv_s[64], lred[2];
    __shared__ float zz_s;
    int b = blockIdx.x, tid = threadIdx.x;

    // parallel u-reduce: 64 partials split 4 ways across 256 threads
    {
        int kk = tid & 63, gg = tid >> 6;
        float s = 0.f;
#pragma unroll
        for (int p = 0; p < 16; p++)
            s += g_Upart[(gg * 16 + p) * BB * KK + b * KK + kk];
        ured[gg][kk] = s;
    }

    // As(lower) = G - S0 - S1 - S2 (upper triangle left untouched/garbage)
    const float* s0 = g_Spart + (NSPLIT * b + 0) * KK * KK;
    const float* s1 = g_Spart + (NSPLIT * b + 1) * KK * KK;
    const float* s2 = g_Spart + (NSPLIT * b + 2) * KK * KK;
#pragma unroll
    for (int i = tid; i < KK * KK; i += 256) {
        int row = i >> 6, col = i & 63;
        if (row >= col)
            As[row * AS_STRIDE + col] = g_G[i] - s0[i] - s1[i] - s2[i];
    }
    __syncthreads();
    if (tid < 64)
        u_s[tid] = ured[0][tid] + ured[1][tid] + ured[2][tid] + ured[3][tid];
    __syncthreads();

    // ---- LDL^T factorization on the lower triangle: one barrier per column --
    int urow = tid >> 6;       // 0..3
    int ucol = tid & 63;       // 0..63
    for (int j = 0; j < 64; j++) {
        float rinv = 1.0f / As[j * AS_STRIDE + j];   // p_j stays at the diagonal
        if (tid == 0) rinv_s[j] = rinv;
        int cc = j + 1 + ucol;
        if (cc < 64) {
            float f = As[cc * AS_STRIDE + j] * rinv;
            for (int rr = j + 1 + urow; rr < 64; rr += 4)
                if (rr >= cc)
                    As[rr * AS_STRIDE + cc] -= As[rr * AS_STRIDE + j] * f;
        }
        __syncthreads();
    }

    // ---- forward solve on warp 0 (reads lower triangle only) ----
    if (tid < 32) {
        float y0 = u_s[tid], y1 = u_s[tid + 32];
        float zz = 0.f;
        for (int j = 0; j < 64; j++) {
            float yj;
            if (j < 32) yj = __shfl_sync(0xffffffffu, y0, j);
            else        yj = __shfl_sync(0xffffffffu, y1, j - 32);
            float wv = yj * rinv_s[j];
            zz += yj * wv;
            if (tid > j)      y0 -= As[tid * AS_STRIDE + j] * wv;
            if (tid + 32 > j) y1 -= As[(tid + 32) * AS_STRIDE + j] * wv;
        }
        if (tid == 0) zz_s = zz;
    }

    // ---- parallel logdet from untouched diagonal p_j ----
    if (tid >= 64 && tid < 128) {
        int j = tid - 64;
        float lg = logf(As[j * AS_STRIDE + j]);
#pragma unroll
        for (int o = 16; o > 0; o >>= 1) lg += __shfl_xor_sync(0xffffffffu, lg, o);
        if ((j & 31) == 0) lred[j >> 5] = lg;
    }
    __syncthreads();

    if (tid == 0) {
        float uni   = g_scal[b * 8 + 0];
        float extra = g_scal[b * 8 + 1];
        float wd2   = g_scal[b * 8 + 2];
        float slp   = g_scal[b * 8 + 3];
        float nb    = g_scal[b * 8 + 4];
        float logdetA = lred[0] + lred[1];
        const float LOG2PI = 1.8378770664093453f;
        float gauss = -0.5f * (nb * LOG2PI + (slp + logdetA) + (wd2 - zz_s));
        out[b] = uni + gauss + extra;
    }
}

// ---------------- launch ------------------------------------------------------
extern "C" void kernel_launch(void* const* d_in, const int* in_sizes, int n_in,
                              void* d_out, int out_size) {
    const float* targets = (const float*)d_in[0];
    const float* rho     = (const float*)d_in[1];
    const float* qs      = (const float*)d_in[2];
    const float* means   = (const float*)d_in[3];
    const float* C       = (const float*)d_in[4];
    const float* psi     = (const float*)d_in[5];
    float* out = (float*)d_out;

    k_gprep<<<NGPART, 256>>>(C, psi);
    k_ew<<<BB, 512>>>(targets, rho, qs, means);
    k_upart<<<dim3(8, NUPART), 256>>>();
    k_syrk<<<BB * NSPLIT, 128>>>();
    k_fact<<<BB, 256>>>(out);
}